// round 1
// baseline (speedup 1.0000x reference)
#include <cuda_runtime.h>
#include <math.h>

#define S    2048
#define NH   32
#define HD   128
#define HID  4096
#define NEGV -1000000000.0f
#define HHSZ 204
#define RECENT 204
#define SEL  (S - RECENT)   // 1844

// ---------------- scratch (static device globals; no allocations) ----------
__device__ float g_q[(size_t)S * HID];
__device__ float g_k[(size_t)S * HID];
__device__ float g_v[(size_t)S * HID];
__device__ float g_attn[(size_t)S * HID];
__device__ float g_scores[(size_t)NH * S * S];   // 512 MB
__device__ float g_rowmax[NH * S];
__device__ float g_rsinv[NH * S];
__device__ float g_hh[NH * S];
__device__ float g_mask[NH * S];

// ---------------- tiled SGEMM, C = alpha * A * B^T (+ causal NEG) ----------
// A: [M,K] row-major lda; B: [N,K] row-major ldb (NT); batched via blockIdx.z
#define BM 128
#define BN 128
#define BK 16

__global__ __launch_bounds__(256) void sgemm_nt(
    const float* __restrict__ A, int lda, size_t sA,
    const float* __restrict__ B, int ldb, size_t sB,
    float* __restrict__ C, int ldc, size_t sC,
    int M, int N, int K, float alpha, int causal)
{
    int bz = blockIdx.z;
    A += (size_t)bz * sA; B += (size_t)bz * sB; C += (size_t)bz * sC;

    __shared__ float As[BK][BM + 4];
    __shared__ float Bs[BK][BN + 4];

    int bm = blockIdx.y * BM, bn = blockIdx.x * BN;
    int tid = threadIdx.x;
    int tr = (tid >> 4) * 8;       // thread tile row offset
    int tc = (tid & 15) * 8;       // thread tile col offset
    int lr = tid >> 2;             // 0..63 (load row)
    int lc = (tid & 3) * 4;        // 0,4,8,12 (load k offset)

    float acc[8][8];
#pragma unroll
    for (int i = 0; i < 8; i++)
#pragma unroll
        for (int j = 0; j < 8; j++) acc[i][j] = 0.f;

    for (int k0 = 0; k0 < K; k0 += BK) {
        float4 a0 = *(const float4*)(A + (size_t)(bm + lr) * lda + k0 + lc);
        float4 a1 = *(const float4*)(A + (size_t)(bm + lr + 64) * lda + k0 + lc);
        float4 b0 = *(const float4*)(B + (size_t)(bn + lr) * ldb + k0 + lc);
        float4 b1 = *(const float4*)(B + (size_t)(bn + lr + 64) * ldb + k0 + lc);
        As[lc + 0][lr] = a0.x; As[lc + 1][lr] = a0.y; As[lc + 2][lr] = a0.z; As[lc + 3][lr] = a0.w;
        As[lc + 0][lr + 64] = a1.x; As[lc + 1][lr + 64] = a1.y; As[lc + 2][lr + 64] = a1.z; As[lc + 3][lr + 64] = a1.w;
        Bs[lc + 0][lr] = b0.x; Bs[lc + 1][lr] = b0.y; Bs[lc + 2][lr] = b0.z; Bs[lc + 3][lr] = b0.w;
        Bs[lc + 0][lr + 64] = b1.x; Bs[lc + 1][lr + 64] = b1.y; Bs[lc + 2][lr + 64] = b1.z; Bs[lc + 3][lr + 64] = b1.w;
        __syncthreads();
#pragma unroll
        for (int kk = 0; kk < BK; kk++) {
            float a[8], b[8];
            *(float4*)(a)     = *(const float4*)&As[kk][tr];
            *(float4*)(a + 4) = *(const float4*)&As[kk][tr + 4];
            *(float4*)(b)     = *(const float4*)&Bs[kk][tc];
            *(float4*)(b + 4) = *(const float4*)&Bs[kk][tc + 4];
#pragma unroll
            for (int i = 0; i < 8; i++)
#pragma unroll
                for (int j = 0; j < 8; j++) acc[i][j] += a[i] * b[j];
        }
        __syncthreads();
    }

#pragma unroll
    for (int i = 0; i < 8; i++) {
        int r = bm + tr + i;
        float out[8];
#pragma unroll
        for (int j = 0; j < 8; j++) {
            float v = acc[i][j] * alpha;
            if (causal && (bn + tc + j) > r) v += NEGV;
            out[j] = v;
        }
        *(float4*)(C + (size_t)r * ldc + bn + tc)     = *(float4*)(out);
        *(float4*)(C + (size_t)r * ldc + bn + tc + 4) = *(float4*)(out + 4);
    }
}

// ---------------- tiled SGEMM, C = A * B (NN), batched -------------------
__global__ __launch_bounds__(256) void sgemm_nn(
    const float* __restrict__ A, int lda, size_t sA,
    const float* __restrict__ B, int ldb, size_t sB,
    float* __restrict__ C, int ldc, size_t sC,
    int M, int N, int K)
{
    int bz = blockIdx.z;
    A += (size_t)bz * sA; B += (size_t)bz * sB; C += (size_t)bz * sC;

    __shared__ float As[BK][BM + 4];
    __shared__ float Bs[BK][BN + 4];

    int bm = blockIdx.y * BM, bn = blockIdx.x * BN;
    int tid = threadIdx.x;
    int tr = (tid >> 4) * 8;
    int tc = (tid & 15) * 8;
    int lr = tid >> 2;             // A load row 0..63
    int lc = (tid & 3) * 4;        // A load k 0,4,8,12
    int lrB = tid >> 5;            // B load k-row 0..7
    int lcB = (tid & 31) * 4;      // B load col 0..124

    float acc[8][8];
#pragma unroll
    for (int i = 0; i < 8; i++)
#pragma unroll
        for (int j = 0; j < 8; j++) acc[i][j] = 0.f;

    for (int k0 = 0; k0 < K; k0 += BK) {
        float4 a0 = *(const float4*)(A + (size_t)(bm + lr) * lda + k0 + lc);
        float4 a1 = *(const float4*)(A + (size_t)(bm + lr + 64) * lda + k0 + lc);
        float4 b0 = *(const float4*)(B + (size_t)(k0 + lrB) * ldb + bn + lcB);
        float4 b1 = *(const float4*)(B + (size_t)(k0 + lrB + 8) * ldb + bn + lcB);
        As[lc + 0][lr] = a0.x; As[lc + 1][lr] = a0.y; As[lc + 2][lr] = a0.z; As[lc + 3][lr] = a0.w;
        As[lc + 0][lr + 64] = a1.x; As[lc + 1][lr + 64] = a1.y; As[lc + 2][lr + 64] = a1.z; As[lc + 3][lr + 64] = a1.w;
        *(float4*)&Bs[lrB][lcB]     = b0;
        *(float4*)&Bs[lrB + 8][lcB] = b1;
        __syncthreads();
#pragma unroll
        for (int kk = 0; kk < BK; kk++) {
            float a[8], b[8];
            *(float4*)(a)     = *(const float4*)&As[kk][tr];
            *(float4*)(a + 4) = *(const float4*)&As[kk][tr + 4];
            *(float4*)(b)     = *(const float4*)&Bs[kk][tc];
            *(float4*)(b + 4) = *(const float4*)&Bs[kk][tc + 4];
#pragma unroll
            for (int i = 0; i < 8; i++)
#pragma unroll
                for (int j = 0; j < 8; j++) acc[i][j] += a[i] * b[j];
        }
        __syncthreads();
    }

#pragma unroll
    for (int i = 0; i < 8; i++) {
        int r = bm + tr + i;
        *(float4*)(C + (size_t)r * ldc + bn + tc)     = *(float4*)(&acc[i][0]);
        *(float4*)(C + (size_t)r * ldc + bn + tc + 4) = *(float4*)(&acc[i][4]);
    }
}

// ---------------- MsPoE rotary (per-head ratio), in-place on q and k ------
__global__ void rope_kernel(float* __restrict__ q, float* __restrict__ k,
                            const int* __restrict__ pos_ids)
{
    int i = blockIdx.x * blockDim.x + threadIdx.x;   // S*NH*64 threads
    int d = i & 63;
    int h = (i >> 6) & 31;
    int s = i >> 11;
    float ratio = 1.2f + (0.6f / 31.0f) * (float)h;
    float t = (float)pos_ids[s] / ratio;
    // inv_freq = 10000^(-d/64) = 2^(-d/64 * log2(10000))
    float inv_freq = exp2f(-(float)d * (13.287712379549449f / 64.0f));
    float f = t * inv_freq;
    float c, sn;
    sincosf(f, &sn, &c);
    size_t base = (size_t)s * HID + h * HD + d;
    float x1 = q[base], x2 = q[base + 64];
    q[base]      = x1 * c - x2 * sn;
    q[base + 64] = x2 * c + x1 * sn;
    x1 = k[base]; x2 = k[base + 64];
    k[base]      = x1 * c - x2 * sn;
    k[base + 64] = x2 * c + x1 * sn;
}

// ---------------- softmax pass 1: per-row max and 1/sum -------------------
__global__ void rowstats_kernel(const float* __restrict__ scores,
                                float* __restrict__ rowmax,
                                float* __restrict__ rsinv)
{
    int q = blockIdx.x, h = blockIdx.y;
    const float* row = scores + ((size_t)h * S + q) * S;
    __shared__ float red[256];
    int tid = threadIdx.x;

    float m = -INFINITY;
    for (int k = tid; k < S; k += 256) m = fmaxf(m, row[k]);
    red[tid] = m; __syncthreads();
    for (int st = 128; st; st >>= 1) {
        if (tid < st) red[tid] = fmaxf(red[tid], red[tid + st]);
        __syncthreads();
    }
    m = red[0];
    __syncthreads();

    float sum = 0.f;
    for (int k = tid; k < S; k += 256) sum += expf(row[k] - m);
    red[tid] = sum; __syncthreads();
    for (int st = 128; st; st >>= 1) {
        if (tid < st) red[tid] += red[tid + st];
        __syncthreads();
    }
    if (tid == 0) {
        rowmax[h * S + q] = m;
        rsinv[h * S + q]  = 1.0f / red[0];
    }
}

// ---------------- hh_score[h][k] = sum_q softmax(scores)[h][q][k] ----------
__global__ void hh_kernel(const float* __restrict__ scores,
                          const float* __restrict__ rowmax,
                          const float* __restrict__ rsinv,
                          float* __restrict__ hh)
{
    int h = blockIdx.y;
    int k = blockIdx.x * 256 + threadIdx.x;
    const float* base = scores + (size_t)h * S * S;
    const float* rm = rowmax + h * S;
    const float* ri = rsinv + h * S;
    float acc = 0.f;
#pragma unroll 4
    for (int q = 0; q < S; q++) {
        acc += expf(base[(size_t)q * S + k] - rm[q]) * ri[q];
    }
    hh[h * S + k] = acc;
}

// ---------------- per-head top-204 over hh[:SEL]; build key mask ----------
__global__ void topk_mask_kernel(const float* __restrict__ hh,
                                 float* __restrict__ mask)
{
    int h = blockIdx.x;
    int tid = threadIdx.x;
    __shared__ float vals[SEL];
    __shared__ float rmax[256];
    __shared__ int   ridx[256];

    for (int i = tid; i < SEL; i += 256) vals[i] = hh[h * S + i];
    for (int k = tid; k < S; k += 256)  mask[h * S + k] = (k >= SEL) ? 0.f : NEGV;
    __syncthreads();

    for (int it = 0; it < HHSZ; it++) {
        float bm = -INFINITY; int bi = SEL;
        for (int i = tid; i < SEL; i += 256) {
            float v = vals[i];
            if (v > bm) { bm = v; bi = i; }
        }
        rmax[tid] = bm; ridx[tid] = bi;
        __syncthreads();
        for (int st = 128; st; st >>= 1) {
            if (tid < st) {
                if (rmax[tid + st] > rmax[tid] ||
                    (rmax[tid + st] == rmax[tid] && ridx[tid + st] < ridx[tid])) {
                    rmax[tid] = rmax[tid + st];
                    ridx[tid] = ridx[tid + st];
                }
            }
            __syncthreads();
        }
        if (tid == 0) {
            int kk = ridx[0];
            mask[h * S + kk] = 0.f;
            vals[kk] = -INFINITY;
        }
        __syncthreads();
    }
}

// ---------------- softmax pass 2 (masked, diag forced visible), in place --
__global__ void softmax2_kernel(float* __restrict__ scores,
                                const float* __restrict__ mask)
{
    int q = blockIdx.x, h = blockIdx.y;
    float* row = scores + ((size_t)h * S + q) * S;
    const float* mk = mask + h * S;
    __shared__ float red[256];
    int tid = threadIdx.x;

    float v[8];
    float m = -INFINITY;
#pragma unroll
    for (int j = 0; j < 8; j++) {
        int k = tid + j * 256;
        float x = row[k] + ((k == q) ? 0.f : mk[k]);
        v[j] = x;
        m = fmaxf(m, x);
    }
    red[tid] = m; __syncthreads();
    for (int st = 128; st; st >>= 1) {
        if (tid < st) red[tid] = fmaxf(red[tid], red[tid + st]);
        __syncthreads();
    }
    m = red[0];
    __syncthreads();

    float sum = 0.f;
#pragma unroll
    for (int j = 0; j < 8; j++) {
        v[j] = expf(v[j] - m);
        sum += v[j];
    }
    red[tid] = sum; __syncthreads();
    for (int st = 128; st; st >>= 1) {
        if (tid < st) red[tid] += red[tid + st];
        __syncthreads();
    }
    float inv = 1.0f / red[0];
#pragma unroll
    for (int j = 0; j < 8; j++) row[tid + j * 256] = v[j] * inv;
}

// ---------------- launch ---------------------------------------------------
extern "C" void kernel_launch(void* const* d_in, const int* in_sizes, int n_in,
                              void* d_out, int out_size)
{
    const float* hs = (const float*)d_in[0];
    const float* Wq = (const float*)d_in[1];
    const float* Wk = (const float*)d_in[2];
    const float* Wv = (const float*)d_in[3];
    const float* Wo = (const float*)d_in[4];
    const int* pos  = (const int*)d_in[5];
    float* out = (float*)d_out;

    float *q, *k, *v, *attn, *scores, *rmax, *rsinv, *hh, *mask;
    cudaGetSymbolAddress((void**)&q, g_q);
    cudaGetSymbolAddress((void**)&k, g_k);
    cudaGetSymbolAddress((void**)&v, g_v);
    cudaGetSymbolAddress((void**)&attn, g_attn);
    cudaGetSymbolAddress((void**)&scores, g_scores);
    cudaGetSymbolAddress((void**)&rmax, g_rowmax);
    cudaGetSymbolAddress((void**)&rsinv, g_rsinv);
    cudaGetSymbolAddress((void**)&hh, g_hh);
    cudaGetSymbolAddress((void**)&mask, g_mask);

    dim3 blk(256);

    // Q/K/V projections: [S,HID] = hs[S,HID] @ W^T (NT)
    dim3 gp(HID / BN, S / BM, 1);
    sgemm_nt<<<gp, blk>>>(hs, HID, 0, Wq, HID, 0, q, HID, 0, S, HID, HID, 1.f, 0);
    sgemm_nt<<<gp, blk>>>(hs, HID, 0, Wk, HID, 0, k, HID, 0, S, HID, HID, 1.f, 0);
    sgemm_nt<<<gp, blk>>>(hs, HID, 0, Wv, HID, 0, v, HID, 0, S, HID, HID, 1.f, 0);

    // rotary
    rope_kernel<<<(S * NH * 64) / 256, 256>>>(q, k, pos);

    // scores[h] = (q_h @ k_h^T) / sqrt(D) + causal  (batched over heads)
    dim3 gs(S / BN, S / BM, NH);
    sgemm_nt<<<gs, blk>>>(q, HID, (size_t)HD, k, HID, (size_t)HD,
                          scores, S, (size_t)S * S,
                          S, S, HD, 0.08838834764831845f, 1);

    // softmax1 row stats + column-summed heavy-hitter scores
    rowstats_kernel<<<dim3(S, NH), 256>>>(scores, rmax, rsinv);
    hh_kernel<<<dim3(S / 256, NH), 256>>>(scores, rmax, rsinv, hh);

    // per-head top-204 + recent-204 mask
    topk_mask_kernel<<<NH, 256>>>(hh, mask);

    // masked softmax (in place over scores)
    softmax2_kernel<<<dim3(S, NH), 256>>>(scores, mask);

    // attn_h = probs2_h @ v_h (NN, batched over heads)
    dim3 gpv(HD / BN, S / BM, NH);
    sgemm_nn<<<gpv, blk>>>(scores, S, (size_t)S * S, v, HID, (size_t)HD,
                           attn, HID, (size_t)HD, S, HD, S);

    // output projection: out = attn @ Wo^T (NT)
    sgemm_nt<<<gp, blk>>>(attn, HID, 0, Wo, HID, 0, out, HID, 0, S, HID, HID, 1.f, 0);
}

// round 3
// speedup vs baseline: 1.0358x; 1.0358x over previous
#include <cuda_runtime.h>
#include <math.h>

#define S    2048
#define NH   32
#define HD   128
#define HID  4096
#define NEGV -1000000000.0f
#define HHSZ 204
#define RECENT 204
#define SEL  (S - RECENT)   // 1844

// ---------------- scratch (static device globals; no allocations) ----------
__device__ float g_q[(size_t)S * HID];
__device__ float g_k[(size_t)S * HID];
__device__ float g_v[(size_t)S * HID];
__device__ float g_attn[(size_t)S * HID];
__device__ float g_scores[(size_t)NH * S * S];   // 512 MB
__device__ float g_rowmax[NH * S];
__device__ float g_rsinv[NH * S];
__device__ float g_hh[NH * S];
__device__ float g_mask[NH * S];

// ---------------- tf32 helpers ---------------------------------------------
__device__ __forceinline__ float tf32r(float x) {
    unsigned r;
    asm("cvt.rna.tf32.f32 %0, %1;" : "=r"(r) : "f"(x));
    return __uint_as_float(r);
}

__device__ __forceinline__ void mma_tf32(float c[4],
                                         unsigned a0, unsigned a1, unsigned a2, unsigned a3,
                                         unsigned b0, unsigned b1)
{
    asm volatile(
        "mma.sync.aligned.m16n8k8.row.col.f32.tf32.tf32.f32 "
        "{%0,%1,%2,%3}, {%4,%5,%6,%7}, {%8,%9}, {%0,%1,%2,%3};"
        : "+f"(c[0]), "+f"(c[1]), "+f"(c[2]), "+f"(c[3])
        : "r"(a0), "r"(a1), "r"(a2), "r"(a3), "r"(b0), "r"(b1));
}

// ---------------- 3xTF32 tensor-core GEMM (fp32-accurate) -------------------
// C[M,N] = alpha * A[M,K] @ op(B)  (+ causal NEG), batched over blockIdx.z.
// NT=true : B is [N,K] row-major (op(B)=B^T)
// NT=false: B is [K,N] row-major (op(B)=B)
// CTA tile 128x128x32; 8 warps, each 32(m) x 64(n); mma m16n8k8.
// Each operand split into big (tf32) + small (tf32 of residual); 3 MMA terms.
#define BM 128
#define BN 128
#define BK 32
#define LDS_S 136   // smem row stride (floats): conflict-free frag loads

template <bool NT>
__global__ __launch_bounds__(256, 2) void mma_gemm3(
    const float* __restrict__ A, int lda, size_t sA,
    const float* __restrict__ B, int ldb, size_t sB,
    float* __restrict__ C, int ldc, size_t sC,
    int K, float alpha, int causal)
{
    int bz = blockIdx.z;
    A += (size_t)bz * sA; B += (size_t)bz * sB; C += (size_t)bz * sC;

    __shared__ float Asb[BK][LDS_S];
    __shared__ float Ass[BK][LDS_S];
    __shared__ float Bsb[BK][LDS_S];
    __shared__ float Bss[BK][LDS_S];

    const int bm = blockIdx.y * BM, bn = blockIdx.x * BN;
    const int tid  = threadIdx.x;
    const int wid  = tid >> 5;
    const int lane = tid & 31;
    const int g  = lane >> 2;   // 0..7
    const int tg = lane & 3;    // 0..3
    const int wm = (wid & 3) * 32;   // warp row offset
    const int wn = (wid >> 2) * 64;  // warp col offset

    // loader indices
    const int lr = tid >> 2;          // 0..63 (A rows / NT-B rows)
    const int kq = (tid & 3) * 8;     // k offset 0,8,16,24
    const int kb = tid >> 3;          // 0..31 (NN-B k row)
    const int cb = (tid & 7) * 16;    // NN-B col base

    float acc[2][8][4];
#pragma unroll
    for (int i = 0; i < 2; i++)
#pragma unroll
        for (int j = 0; j < 8; j++)
#pragma unroll
            for (int t = 0; t < 4; t++) acc[i][j][t] = 0.f;

    for (int k0 = 0; k0 < K; k0 += BK) {
        // ---- A tile: [bm..bm+127] x [k0..k0+31], store transposed As[k][m]
        {
            const float* Ab = A + (size_t)(bm + lr) * lda + k0 + kq;
#pragma unroll
            for (int half = 0; half < 2; half++) {
                int ro = lr + half * 64;
                const float* p = Ab + (size_t)half * 64 * lda;
                float4 x0 = *(const float4*)(p);
                float4 x1 = *(const float4*)(p + 4);
                float xv[8] = {x0.x, x0.y, x0.z, x0.w, x1.x, x1.y, x1.z, x1.w};
#pragma unroll
                for (int j = 0; j < 8; j++) {
                    float big = tf32r(xv[j]);
                    Asb[kq + j][ro] = big;
                    Ass[kq + j][ro] = tf32r(xv[j] - big);
                }
            }
        }
        // ---- B tile -> Bs[k][n]
        if (NT) {
            const float* Bb = B + (size_t)(bn + lr) * ldb + k0 + kq;
#pragma unroll
            for (int half = 0; half < 2; half++) {
                int ro = lr + half * 64;
                const float* p = Bb + (size_t)half * 64 * ldb;
                float4 x0 = *(const float4*)(p);
                float4 x1 = *(const float4*)(p + 4);
                float xv[8] = {x0.x, x0.y, x0.z, x0.w, x1.x, x1.y, x1.z, x1.w};
#pragma unroll
                for (int j = 0; j < 8; j++) {
                    float big = tf32r(xv[j]);
                    Bsb[kq + j][ro] = big;
                    Bss[kq + j][ro] = tf32r(xv[j] - big);
                }
            }
        } else {
            const float* Bb = B + (size_t)(k0 + kb) * ldb + bn + cb;
#pragma unroll
            for (int qv = 0; qv < 4; qv++) {
                float4 x = *(const float4*)(Bb + qv * 4);
                float xv[4] = {x.x, x.y, x.z, x.w};
#pragma unroll
                for (int j = 0; j < 4; j++) {
                    float big = tf32r(xv[j]);
                    Bsb[kb][cb + qv * 4 + j] = big;
                    Bss[kb][cb + qv * 4 + j] = tf32r(xv[j] - big);
                }
            }
        }
        __syncthreads();

#pragma unroll
        for (int kk = 0; kk < 4; kk++) {
            const int kr = kk * 8;
            unsigned ab[2][4], as[2][4];
#pragma unroll
            for (int mi = 0; mi < 2; mi++) {
                int rm = wm + mi * 16;
                ab[mi][0] = __float_as_uint(Asb[kr + tg    ][rm + g    ]);
                ab[mi][1] = __float_as_uint(Asb[kr + tg    ][rm + g + 8]);
                ab[mi][2] = __float_as_uint(Asb[kr + tg + 4][rm + g    ]);
                ab[mi][3] = __float_as_uint(Asb[kr + tg + 4][rm + g + 8]);
                as[mi][0] = __float_as_uint(Ass[kr + tg    ][rm + g    ]);
                as[mi][1] = __float_as_uint(Ass[kr + tg    ][rm + g + 8]);
                as[mi][2] = __float_as_uint(Ass[kr + tg + 4][rm + g    ]);
                as[mi][3] = __float_as_uint(Ass[kr + tg + 4][rm + g + 8]);
            }
#pragma unroll
            for (int ni = 0; ni < 8; ni++) {
                int cn = wn + ni * 8;
                unsigned bb0 = __float_as_uint(Bsb[kr + tg    ][cn + g]);
                unsigned bb1 = __float_as_uint(Bsb[kr + tg + 4][cn + g]);
                unsigned bs0 = __float_as_uint(Bss[kr + tg    ][cn + g]);
                unsigned bs1 = __float_as_uint(Bss[kr + tg + 4][cn + g]);
#pragma unroll
                for (int mi = 0; mi < 2; mi++) {
                    // small terms first, big last (fp32 accumulate)
                    mma_tf32(acc[mi][ni], ab[mi][0], ab[mi][1], ab[mi][2], ab[mi][3], bs0, bs1);
                    mma_tf32(acc[mi][ni], as[mi][0], as[mi][1], as[mi][2], as[mi][3], bb0, bb1);
                    mma_tf32(acc[mi][ni], ab[mi][0], ab[mi][1], ab[mi][2], ab[mi][3], bb0, bb1);
                }
            }
        }
        __syncthreads();
    }

    // ---- epilogue: alpha, optional causal, store
#pragma unroll
    for (int mi = 0; mi < 2; mi++) {
#pragma unroll
        for (int ni = 0; ni < 8; ni++) {
            int r0 = bm + wm + mi * 16 + g;
            int c0 = bn + wn + ni * 8 + tg * 2;
            float v0 = acc[mi][ni][0] * alpha;
            float v1 = acc[mi][ni][1] * alpha;
            float v2 = acc[mi][ni][2] * alpha;
            float v3 = acc[mi][ni][3] * alpha;
            if (causal) {
                if (c0     > r0)     v0 += NEGV;
                if (c0 + 1 > r0)     v1 += NEGV;
                if (c0     > r0 + 8) v2 += NEGV;
                if (c0 + 1 > r0 + 8) v3 += NEGV;
            }
            *(float2*)(C + (size_t)r0 * ldc + c0)       = make_float2(v0, v1);
            *(float2*)(C + (size_t)(r0 + 8) * ldc + c0) = make_float2(v2, v3);
        }
    }
}

// ---------------- MsPoE rotary (per-head ratio), in-place on q and k ------
__global__ void rope_kernel(float* __restrict__ q, float* __restrict__ k,
                            const int* __restrict__ pos_ids)
{
    int i = blockIdx.x * blockDim.x + threadIdx.x;   // S*NH*64 threads
    int d = i & 63;
    int h = (i >> 6) & 31;
    int s = i >> 11;
    float ratio = 1.2f + (0.6f / 31.0f) * (float)h;
    float t = (float)pos_ids[s] / ratio;
    float inv_freq = exp2f(-(float)d * (13.287712379549449f / 64.0f));
    float f = t * inv_freq;
    float c, sn;
    sincosf(f, &sn, &c);
    size_t base = (size_t)s * HID + h * HD + d;
    float x1 = q[base], x2 = q[base + 64];
    q[base]      = x1 * c - x2 * sn;
    q[base + 64] = x2 * c + x1 * sn;
    x1 = k[base]; x2 = k[base + 64];
    k[base]      = x1 * c - x2 * sn;
    k[base + 64] = x2 * c + x1 * sn;
}

// ---------------- softmax pass 1: per-row max and 1/sum -------------------
__global__ void rowstats_kernel(const float* __restrict__ scores,
                                float* __restrict__ rowmax,
                                float* __restrict__ rsinv)
{
    int q = blockIdx.x, h = blockIdx.y;
    const float* row = scores + ((size_t)h * S + q) * S;
    __shared__ float red[256];
    int tid = threadIdx.x;

    float m = -INFINITY;
    for (int k = tid; k < S; k += 256) m = fmaxf(m, row[k]);
    red[tid] = m; __syncthreads();
    for (int st = 128; st; st >>= 1) {
        if (tid < st) red[tid] = fmaxf(red[tid], red[tid + st]);
        __syncthreads();
    }
    m = red[0];
    __syncthreads();

    float sum = 0.f;
    for (int k = tid; k < S; k += 256) sum += expf(row[k] - m);
    red[tid] = sum; __syncthreads();
    for (int st = 128; st; st >>= 1) {
        if (tid < st) red[tid] += red[tid + st];
        __syncthreads();
    }
    if (tid == 0) {
        rowmax[h * S + q] = m;
        rsinv[h * S + q]  = 1.0f / red[0];
    }
}

// ---------------- hh_score[h][k] = sum_q softmax(scores)[h][q][k] ----------
__global__ void hh_kernel(const float* __restrict__ scores,
                          const float* __restrict__ rowmax,
                          const float* __restrict__ rsinv,
                          float* __restrict__ hh)
{
    int h = blockIdx.y;
    int k = blockIdx.x * 256 + threadIdx.x;
    const float* base = scores + (size_t)h * S * S;
    const float* rm = rowmax + h * S;
    const float* ri = rsinv + h * S;
    float acc = 0.f;
#pragma unroll 4
    for (int q = 0; q < S; q++) {
        acc += expf(base[(size_t)q * S + k] - rm[q]) * ri[q];
    }
    hh[h * S + k] = acc;
}

// ---------------- per-head top-204 over hh[:SEL]; build key mask ----------
__global__ void topk_mask_kernel(const float* __restrict__ hh,
                                 float* __restrict__ mask)
{
    int h = blockIdx.x;
    int tid = threadIdx.x;
    __shared__ float vals[SEL];
    __shared__ float rmax[256];
    __shared__ int   ridx[256];

    for (int i = tid; i < SEL; i += 256) vals[i] = hh[h * S + i];
    for (int k = tid; k < S; k += 256)  mask[h * S + k] = (k >= SEL) ? 0.f : NEGV;
    __syncthreads();

    for (int it = 0; it < HHSZ; it++) {
        float bm = -INFINITY; int bi = SEL;
        for (int i = tid; i < SEL; i += 256) {
            float v = vals[i];
            if (v > bm) { bm = v; bi = i; }
        }
        rmax[tid] = bm; ridx[tid] = bi;
        __syncthreads();
        for (int st = 128; st; st >>= 1) {
            if (tid < st) {
                if (rmax[tid + st] > rmax[tid] ||
                    (rmax[tid + st] == rmax[tid] && ridx[tid + st] < ridx[tid])) {
                    rmax[tid] = rmax[tid + st];
                    ridx[tid] = ridx[tid + st];
                }
            }
            __syncthreads();
        }
        if (tid == 0) {
            int kk = ridx[0];
            mask[h * S + kk] = 0.f;
            vals[kk] = -INFINITY;
        }
        __syncthreads();
    }
}

// ---------------- softmax pass 2 (masked, diag forced visible), in place --
__global__ void softmax2_kernel(float* __restrict__ scores,
                                const float* __restrict__ mask)
{
    int q = blockIdx.x, h = blockIdx.y;
    float* row = scores + ((size_t)h * S + q) * S;
    const float* mk = mask + h * S;
    __shared__ float red[256];
    int tid = threadIdx.x;

    float v[8];
    float m = -INFINITY;
#pragma unroll
    for (int j = 0; j < 8; j++) {
        int k = tid + j * 256;
        float x = row[k] + ((k == q) ? 0.f : mk[k]);
        v[j] = x;
        m = fmaxf(m, x);
    }
    red[tid] = m; __syncthreads();
    for (int st = 128; st; st >>= 1) {
        if (tid < st) red[tid] = fmaxf(red[tid], red[tid + st]);
        __syncthreads();
    }
    m = red[0];
    __syncthreads();

    float sum = 0.f;
#pragma unroll
    for (int j = 0; j < 8; j++) {
        v[j] = expf(v[j] - m);
        sum += v[j];
    }
    red[tid] = sum; __syncthreads();
    for (int st = 128; st; st >>= 1) {
        if (tid < st) red[tid] += red[tid + st];
        __syncthreads();
    }
    float inv = 1.0f / red[0];
#pragma unroll
    for (int j = 0; j < 8; j++) row[tid + j * 256] = v[j] * inv;
}

// ---------------- launch ---------------------------------------------------
extern "C" void kernel_launch(void* const* d_in, const int* in_sizes, int n_in,
                              void* d_out, int out_size)
{
    const float* hs = (const float*)d_in[0];
    const float* Wq = (const float*)d_in[1];
    const float* Wk = (const float*)d_in[2];
    const float* Wv = (const float*)d_in[3];
    const float* Wo = (const float*)d_in[4];
    const int* pos  = (const int*)d_in[5];
    float* out = (float*)d_out;

    float *q, *k, *v, *attn, *scores, *rmax, *rsinv, *hh, *mask;
    cudaGetSymbolAddress((void**)&q, g_q);
    cudaGetSymbolAddress((void**)&k, g_k);
    cudaGetSymbolAddress((void**)&v, g_v);
    cudaGetSymbolAddress((void**)&attn, g_attn);
    cudaGetSymbolAddress((void**)&scores, g_scores);
    cudaGetSymbolAddress((void**)&rmax, g_rowmax);
    cudaGetSymbolAddress((void**)&rsinv, g_rsinv);
    cudaGetSymbolAddress((void**)&hh, g_hh);
    cudaGetSymbolAddress((void**)&mask, g_mask);

    dim3 blk(256);

    // Q/K/V projections: [S,HID] = hs[S,HID] @ W^T (NT)
    dim3 gp(HID / BN, S / BM, 1);
    mma_gemm3<true><<<gp, blk>>>(hs, HID, 0, Wq, HID, 0, q, HID, 0, HID, 1.f, 0);
    mma_gemm3<true><<<gp, blk>>>(hs, HID, 0, Wk, HID, 0, k, HID, 0, HID, 1.f, 0);
    mma_gemm3<true><<<gp, blk>>>(hs, HID, 0, Wv, HID, 0, v, HID, 0, HID, 1.f, 0);

    // rotary
    rope_kernel<<<(S * NH * 64) / 256, 256>>>(q, k, pos);

    // scores[h] = (q_h @ k_h^T) / sqrt(D) + causal  (batched over heads)
    dim3 gs(S / BN, S / BM, NH);
    mma_gemm3<true><<<gs, blk>>>(q, HID, (size_t)HD, k, HID, (size_t)HD,
                                 scores, S, (size_t)S * S,
                                 HD, 0.08838834764831845f, 1);

    // softmax1 row stats + column-summed heavy-hitter scores
    rowstats_kernel<<<dim3(S, NH), 256>>>(scores, rmax, rsinv);
    hh_kernel<<<dim3(S / 256, NH), 256>>>(scores, rmax, rsinv, hh);

    // per-head top-204 + recent-204 mask
    topk_mask_kernel<<<NH, 256>>>(hh, mask);

    // masked softmax (in place over scores)
    softmax2_kernel<<<dim3(S, NH), 256>>>(scores, mask);

    // attn_h = probs2_h @ v_h (NN, batched over heads)
    dim3 gpv(HD / BN, S / BM, NH);
    mma_gemm3<false><<<gpv, blk>>>(scores, S, (size_t)S * S, v, HID, (size_t)HD,
                                   attn, HID, (size_t)HD, S, 1.f, 0);

    // output projection: out = attn @ Wo^T (NT)
    mma_gemm3<true><<<gp, blk>>>(attn, HID, 0, Wo, HID, 0, out, HID, 0, HID, 1.f, 0);
}

// round 4
// speedup vs baseline: 1.9436x; 1.8764x over previous
#include <cuda_runtime.h>
#include <cuda_bf16.h>
#include <math.h>
#include <string.h>

#define S    2048
#define NH   32
#define HD   128
#define HID  4096
#define NEGV -1000000000.0f
#define HHSZ 204
#define RECENT 204
#define SEL  (S - RECENT)   // 1844

// ---------------- scratch (static device globals; no allocations) ----------
__device__ float g_q[(size_t)S * HID];
__device__ float g_k[(size_t)S * HID];
__device__ float g_v[(size_t)S * HID];
__device__ float g_attn[(size_t)S * HID];
__device__ float g_scores[(size_t)NH * S * S];   // 512 MB
__device__ float g_rowmax[NH * S];
__device__ float g_rsinv[NH * S];
__device__ float g_hh[NH * S];
__device__ float g_mask[NH * S];

// ---------------- bf16 split helpers ----------------------------------------
__device__ __forceinline__ void split2(float e0, float e1,
                                       unsigned &ub, unsigned &us)
{
    __nv_bfloat16 b0 = __float2bfloat16(e0);
    __nv_bfloat16 b1 = __float2bfloat16(e1);
    float r0 = e0 - __bfloat162float(b0);
    float r1 = e1 - __bfloat162float(b1);
    __nv_bfloat16 s0 = __float2bfloat16(r0);
    __nv_bfloat16 s1 = __float2bfloat16(r1);
    unsigned lb, hb, ls, hs;
    lb = (unsigned)*(unsigned short*)&b0;
    hb = (unsigned)*(unsigned short*)&b1;
    ls = (unsigned)*(unsigned short*)&s0;
    hs = (unsigned)*(unsigned short*)&s1;
    ub = lb | (hb << 16);
    us = ls | (hs << 16);
}

__device__ __forceinline__ void mma_bf16(float c[4],
                                         unsigned a0, unsigned a1, unsigned a2, unsigned a3,
                                         unsigned b0, unsigned b1)
{
    asm volatile(
        "mma.sync.aligned.m16n8k16.row.col.f32.bf16.bf16.f32 "
        "{%0,%1,%2,%3}, {%4,%5,%6,%7}, {%8,%9}, {%0,%1,%2,%3};"
        : "+f"(c[0]), "+f"(c[1]), "+f"(c[2]), "+f"(c[3])
        : "r"(a0), "r"(a1), "r"(a2), "r"(a3), "r"(b0), "r"(b1));
}

// ---------------- bf16x3 tensor-core GEMM (fp32-accurate) -------------------
// C[M,N] = alpha * A[M,K] @ op(B)  (+ causal NEG), batched over blockIdx.z.
// NT=true : B is [N,K] row-major (op(B)=B^T)
// NT=false: B is [K,N] row-major (op(B)=B)
// CTA tile 128x128x32; 8 warps, each 32(m) x 64(n); mma m16n8k16.
// smem stores k-pairs as bf16x2 in u32; row stride 20 u32 (conflict-free).
#define BM 128
#define BN 128
#define BK 32
#define KP 20   // u32 row stride: 16 k-pairs + 4 pad

template <bool NT>
__global__ __launch_bounds__(256, 2) void mma_gemm_bf3(
    const float* __restrict__ A, int lda, size_t sA,
    const float* __restrict__ B, int ldb, size_t sB,
    float* __restrict__ C, int ldc, size_t sC,
    int K, float alpha, int causal)
{
    int bz = blockIdx.z;
    A += (size_t)bz * sA; B += (size_t)bz * sB; C += (size_t)bz * sC;

    __shared__ unsigned Asb[BM][KP];
    __shared__ unsigned Ass[BM][KP];
    __shared__ unsigned Bsb[BN][KP];
    __shared__ unsigned Bss[BN][KP];

    const int bm = blockIdx.y * BM, bn = blockIdx.x * BN;
    const int tid  = threadIdx.x;
    const int wid  = tid >> 5;
    const int lane = tid & 31;
    const int g  = lane >> 2;   // 0..7
    const int tg = lane & 3;    // 0..3
    const int wm = (wid & 3) * 32;   // warp row offset
    const int wn = (wid >> 2) * 64;  // warp col offset

    // loader indices (A and NT-B): row lr, k floats kq..kq+7
    const int lr = tid >> 2;          // 0..63
    const int kq = (tid & 3) * 8;     // 0,8,16,24
    // NN-B loader: two k rows, 8 columns
    const int kb2 = (tid >> 4) * 2;   // 0..30 step 2
    const int cb8 = (tid & 15) * 8;   // 0..120 step 8

    float acc[2][8][4];
#pragma unroll
    for (int i = 0; i < 2; i++)
#pragma unroll
        for (int j = 0; j < 8; j++)
#pragma unroll
            for (int t = 0; t < 4; t++) acc[i][j][t] = 0.f;

    for (int k0 = 0; k0 < K; k0 += BK) {
        // ---- A tile -> Asb/Ass[m][kpair]
        {
            const float* Ap = A + (size_t)(bm + lr) * lda + k0 + kq;
#pragma unroll
            for (int half = 0; half < 2; half++) {
                int row = lr + half * 64;
                const float* p = Ap + (size_t)half * 64 * lda;
                float4 x0 = *(const float4*)(p);
                float4 x1 = *(const float4*)(p + 4);
                unsigned ub[4], us[4];
                split2(x0.x, x0.y, ub[0], us[0]);
                split2(x0.z, x0.w, ub[1], us[1]);
                split2(x1.x, x1.y, ub[2], us[2]);
                split2(x1.z, x1.w, ub[3], us[3]);
                *(uint4*)&Asb[row][kq >> 1] = make_uint4(ub[0], ub[1], ub[2], ub[3]);
                *(uint4*)&Ass[row][kq >> 1] = make_uint4(us[0], us[1], us[2], us[3]);
            }
        }
        // ---- B tile -> Bsb/Bss[n][kpair]
        if (NT) {
            const float* Bp = B + (size_t)(bn + lr) * ldb + k0 + kq;
#pragma unroll
            for (int half = 0; half < 2; half++) {
                int row = lr + half * 64;
                const float* p = Bp + (size_t)half * 64 * ldb;
                float4 x0 = *(const float4*)(p);
                float4 x1 = *(const float4*)(p + 4);
                unsigned ub[4], us[4];
                split2(x0.x, x0.y, ub[0], us[0]);
                split2(x0.z, x0.w, ub[1], us[1]);
                split2(x1.x, x1.y, ub[2], us[2]);
                split2(x1.z, x1.w, ub[3], us[3]);
                *(uint4*)&Bsb[row][kq >> 1] = make_uint4(ub[0], ub[1], ub[2], ub[3]);
                *(uint4*)&Bss[row][kq >> 1] = make_uint4(us[0], us[1], us[2], us[3]);
            }
        } else {
            const float* p0 = B + (size_t)(k0 + kb2) * ldb + bn + cb8;
            const float* p1 = p0 + ldb;
            float4 y0 = *(const float4*)(p0);
            float4 y1 = *(const float4*)(p0 + 4);
            float4 z0 = *(const float4*)(p1);
            float4 z1 = *(const float4*)(p1 + 4);
            float ye[8] = {y0.x, y0.y, y0.z, y0.w, y1.x, y1.y, y1.z, y1.w};
            float ze[8] = {z0.x, z0.y, z0.z, z0.w, z1.x, z1.y, z1.z, z1.w};
            int kp = kb2 >> 1;
#pragma unroll
            for (int j = 0; j < 8; j++) {
                unsigned ub, us;
                split2(ye[j], ze[j], ub, us);   // pair = {k, k+1} for column n
                Bsb[cb8 + j][kp] = ub;
                Bss[cb8 + j][kp] = us;
            }
        }
        __syncthreads();

#pragma unroll
        for (int kk = 0; kk < 2; kk++) {
            const int p0 = kk * 8 + tg;      // pair index for a0/a1/b0
            const int p1 = p0 + 4;           // pair index for a2/a3/b1
            unsigned ab[2][4], as[2][4];
#pragma unroll
            for (int mi = 0; mi < 2; mi++) {
                int rm = wm + mi * 16;
                ab[mi][0] = Asb[rm + g    ][p0];
                ab[mi][1] = Asb[rm + g + 8][p0];
                ab[mi][2] = Asb[rm + g    ][p1];
                ab[mi][3] = Asb[rm + g + 8][p1];
                as[mi][0] = Ass[rm + g    ][p0];
                as[mi][1] = Ass[rm + g + 8][p0];
                as[mi][2] = Ass[rm + g    ][p1];
                as[mi][3] = Ass[rm + g + 8][p1];
            }
#pragma unroll
            for (int ni = 0; ni < 8; ni++) {
                int cn = wn + ni * 8 + g;
                unsigned bb0 = Bsb[cn][p0];
                unsigned bb1 = Bsb[cn][p1];
                unsigned bs0 = Bss[cn][p0];
                unsigned bs1 = Bss[cn][p1];
#pragma unroll
                for (int mi = 0; mi < 2; mi++) {
                    // small terms first, big last (fp32 accumulate)
                    mma_bf16(acc[mi][ni], ab[mi][0], ab[mi][1], ab[mi][2], ab[mi][3], bs0, bs1);
                    mma_bf16(acc[mi][ni], as[mi][0], as[mi][1], as[mi][2], as[mi][3], bb0, bb1);
                    mma_bf16(acc[mi][ni], ab[mi][0], ab[mi][1], ab[mi][2], ab[mi][3], bb0, bb1);
                }
            }
        }
        __syncthreads();
    }

    // ---- epilogue: alpha, optional causal, store
#pragma unroll
    for (int mi = 0; mi < 2; mi++) {
#pragma unroll
        for (int ni = 0; ni < 8; ni++) {
            int r0 = bm + wm + mi * 16 + g;
            int c0 = bn + wn + ni * 8 + tg * 2;
            float v0 = acc[mi][ni][0] * alpha;
            float v1 = acc[mi][ni][1] * alpha;
            float v2 = acc[mi][ni][2] * alpha;
            float v3 = acc[mi][ni][3] * alpha;
            if (causal) {
                if (c0     > r0)     v0 += NEGV;
                if (c0 + 1 > r0)     v1 += NEGV;
                if (c0     > r0 + 8) v2 += NEGV;
                if (c0 + 1 > r0 + 8) v3 += NEGV;
            }
            *(float2*)(C + (size_t)r0 * ldc + c0)       = make_float2(v0, v1);
            *(float2*)(C + (size_t)(r0 + 8) * ldc + c0) = make_float2(v2, v3);
        }
    }
}

// ---------------- MsPoE rotary (per-head ratio), in-place on q and k ------
__global__ void rope_kernel(float* __restrict__ q, float* __restrict__ k,
                            const int* __restrict__ pos_ids)
{
    int i = blockIdx.x * blockDim.x + threadIdx.x;   // S*NH*64 threads
    int d = i & 63;
    int h = (i >> 6) & 31;
    int s = i >> 11;
    float ratio = 1.2f + (0.6f / 31.0f) * (float)h;
    float t = (float)pos_ids[s] / ratio;
    float inv_freq = exp2f(-(float)d * (13.287712379549449f / 64.0f));
    float f = t * inv_freq;
    float c, sn;
    sincosf(f, &sn, &c);
    size_t base = (size_t)s * HID + h * HD + d;
    float x1 = q[base], x2 = q[base + 64];
    q[base]      = x1 * c - x2 * sn;
    q[base + 64] = x2 * c + x1 * sn;
    x1 = k[base]; x2 = k[base + 64];
    k[base]      = x1 * c - x2 * sn;
    k[base + 64] = x2 * c + x1 * sn;
}

// ---------------- softmax pass 1: per-row max and 1/sum -------------------
__global__ void rowstats_kernel(const float* __restrict__ scores,
                                float* __restrict__ rowmax,
                                float* __restrict__ rsinv)
{
    int q = blockIdx.x, h = blockIdx.y;
    const float* row = scores + ((size_t)h * S + q) * S;
    __shared__ float red[256];
    int tid = threadIdx.x;

    float m = -INFINITY;
    for (int k = tid; k < S; k += 256) m = fmaxf(m, row[k]);
    red[tid] = m; __syncthreads();
    for (int st = 128; st; st >>= 1) {
        if (tid < st) red[tid] = fmaxf(red[tid], red[tid + st]);
        __syncthreads();
    }
    m = red[0];
    __syncthreads();

    float sum = 0.f;
    for (int k = tid; k < S; k += 256) sum += expf(row[k] - m);
    red[tid] = sum; __syncthreads();
    for (int st = 128; st; st >>= 1) {
        if (tid < st) red[tid] += red[tid + st];
        __syncthreads();
    }
    if (tid == 0) {
        rowmax[h * S + q] = m;
        rsinv[h * S + q]  = 1.0f / red[0];
    }
}

// ---------------- hh_score[h][k] = sum_q softmax(scores)[h][q][k] ----------
__global__ void hh_kernel(const float* __restrict__ scores,
                          const float* __restrict__ rowmax,
                          const float* __restrict__ rsinv,
                          float* __restrict__ hh)
{
    int h = blockIdx.y;
    int k = blockIdx.x * 256 + threadIdx.x;
    const float* base = scores + (size_t)h * S * S;
    const float* rm = rowmax + h * S;
    const float* ri = rsinv + h * S;
    float acc = 0.f;
#pragma unroll 4
    for (int q = 0; q < S; q++) {
        acc += expf(base[(size_t)q * S + k] - rm[q]) * ri[q];
    }
    hh[h * S + k] = acc;
}

// ---------------- per-head top-204 over hh[:SEL]; build key mask ----------
__global__ void topk_mask_kernel(const float* __restrict__ hh,
                                 float* __restrict__ mask)
{
    int h = blockIdx.x;
    int tid = threadIdx.x;
    __shared__ float vals[SEL];
    __shared__ float rmax[256];
    __shared__ int   ridx[256];

    for (int i = tid; i < SEL; i += 256) vals[i] = hh[h * S + i];
    for (int k = tid; k < S; k += 256)  mask[h * S + k] = (k >= SEL) ? 0.f : NEGV;
    __syncthreads();

    for (int it = 0; it < HHSZ; it++) {
        float bm = -INFINITY; int bi = SEL;
        for (int i = tid; i < SEL; i += 256) {
            float v = vals[i];
            if (v > bm) { bm = v; bi = i; }
        }
        rmax[tid] = bm; ridx[tid] = bi;
        __syncthreads();
        for (int st = 128; st; st >>= 1) {
            if (tid < st) {
                if (rmax[tid + st] > rmax[tid] ||
                    (rmax[tid + st] == rmax[tid] && ridx[tid + st] < ridx[tid])) {
                    rmax[tid] = rmax[tid + st];
                    ridx[tid] = ridx[tid + st];
                }
            }
            __syncthreads();
        }
        if (tid == 0) {
            int kk = ridx[0];
            mask[h * S + kk] = 0.f;
            vals[kk] = -INFINITY;
        }
        __syncthreads();
    }
}

// ---------------- softmax pass 2 (masked, diag forced visible), in place --
__global__ void softmax2_kernel(float* __restrict__ scores,
                                const float* __restrict__ mask)
{
    int q = blockIdx.x, h = blockIdx.y;
    float* row = scores + ((size_t)h * S + q) * S;
    const float* mk = mask + h * S;
    __shared__ float red[256];
    int tid = threadIdx.x;

    float v[8];
    float m = -INFINITY;
#pragma unroll
    for (int j = 0; j < 8; j++) {
        int k = tid + j * 256;
        float x = row[k] + ((k == q) ? 0.f : mk[k]);
        v[j] = x;
        m = fmaxf(m, x);
    }
    red[tid] = m; __syncthreads();
    for (int st = 128; st; st >>= 1) {
        if (tid < st) red[tid] = fmaxf(red[tid], red[tid + st]);
        __syncthreads();
    }
    m = red[0];
    __syncthreads();

    float sum = 0.f;
#pragma unroll
    for (int j = 0; j < 8; j++) {
        v[j] = expf(v[j] - m);
        sum += v[j];
    }
    red[tid] = sum; __syncthreads();
    for (int st = 128; st; st >>= 1) {
        if (tid < st) red[tid] += red[tid + st];
        __syncthreads();
    }
    float inv = 1.0f / red[0];
#pragma unroll
    for (int j = 0; j < 8; j++) row[tid + j * 256] = v[j] * inv;
}

// ---------------- launch ---------------------------------------------------
extern "C" void kernel_launch(void* const* d_in, const int* in_sizes, int n_in,
                              void* d_out, int out_size)
{
    const float* hs = (const float*)d_in[0];
    const float* Wq = (const float*)d_in[1];
    const float* Wk = (const float*)d_in[2];
    const float* Wv = (const float*)d_in[3];
    const float* Wo = (const float*)d_in[4];
    const int* pos  = (const int*)d_in[5];
    float* out = (float*)d_out;

    float *q, *k, *v, *attn, *scores, *rmax, *rsinv, *hh, *mask;
    cudaGetSymbolAddress((void**)&q, g_q);
    cudaGetSymbolAddress((void**)&k, g_k);
    cudaGetSymbolAddress((void**)&v, g_v);
    cudaGetSymbolAddress((void**)&attn, g_attn);
    cudaGetSymbolAddress((void**)&scores, g_scores);
    cudaGetSymbolAddress((void**)&rmax, g_rowmax);
    cudaGetSymbolAddress((void**)&rsinv, g_rsinv);
    cudaGetSymbolAddress((void**)&hh, g_hh);
    cudaGetSymbolAddress((void**)&mask, g_mask);

    dim3 blk(256);

    // Q/K/V projections: [S,HID] = hs[S,HID] @ W^T (NT)
    dim3 gp(HID / BN, S / BM, 1);
    mma_gemm_bf3<true><<<gp, blk>>>(hs, HID, 0, Wq, HID, 0, q, HID, 0, HID, 1.f, 0);
    mma_gemm_bf3<true><<<gp, blk>>>(hs, HID, 0, Wk, HID, 0, k, HID, 0, HID, 1.f, 0);
    mma_gemm_bf3<true><<<gp, blk>>>(hs, HID, 0, Wv, HID, 0, v, HID, 0, HID, 1.f, 0);

    // rotary
    rope_kernel<<<(S * NH * 64) / 256, 256>>>(q, k, pos);

    // scores[h] = (q_h @ k_h^T) / sqrt(D) + causal  (batched over heads)
    dim3 gs(S / BN, S / BM, NH);
    mma_gemm_bf3<true><<<gs, blk>>>(q, HID, (size_t)HD, k, HID, (size_t)HD,
                                    scores, S, (size_t)S * S,
                                    HD, 0.08838834764831845f, 1);

    // softmax1 row stats + column-summed heavy-hitter scores
    rowstats_kernel<<<dim3(S, NH), 256>>>(scores, rmax, rsinv);
    hh_kernel<<<dim3(S / 256, NH), 256>>>(scores, rmax, rsinv, hh);

    // per-head top-204 + recent-204 mask
    topk_mask_kernel<<<NH, 256>>>(hh, mask);

    // masked softmax (in place over scores)
    softmax2_kernel<<<dim3(S, NH), 256>>>(scores, mask);

    // attn_h = probs2_h @ v_h (NN, batched over heads)
    dim3 gpv(HD / BN, S / BM, NH);
    mma_gemm_bf3<false><<<gpv, blk>>>(scores, S, (size_t)S * S, v, HID, (size_t)HD,
                                      attn, HID, (size_t)HD, S, 1.f, 0);

    // output projection: out = attn @ Wo^T (NT)
    mma_gemm_bf3<true><<<gp, blk>>>(attn, HID, 0, Wo, HID, 0, out, HID, 0, HID, 1.f, 0);
}

// round 5
// speedup vs baseline: 2.2982x; 1.1824x over previous
#include <cuda_runtime.h>
#include <cuda_bf16.h>
#include <math.h>

#define S    2048
#define NH   32
#define HD   128
#define HID  4096
#define NEGV -1000000000.0f
#define HHSZ 204
#define RECENT 204
#define SEL  (S - RECENT)   // 1844

typedef __nv_bfloat16 bf16;

// ---------------- scratch (static device globals; no allocations) ----------
__device__ float g_q[(size_t)S * HID];
__device__ float g_k[(size_t)S * HID];
__device__ float g_scores[(size_t)NH * S * S];   // 512 MB
__device__ float g_rowmax[NH * S];
__device__ float g_rsinv[NH * S];
__device__ float g_hh[NH * S];
__device__ float g_mask[NH * S];

__device__ bf16 g_hs_b[(size_t)S * HID],  g_hs_s[(size_t)S * HID];
__device__ bf16 g_w_b[4][(size_t)HID * HID], g_w_s[4][(size_t)HID * HID];
__device__ bf16 g_qb[(size_t)S * HID], g_qs[(size_t)S * HID];
__device__ bf16 g_kb[(size_t)S * HID], g_ks[(size_t)S * HID];
__device__ bf16 g_vb[(size_t)S * HID], g_vs[(size_t)S * HID];
__device__ bf16 g_pb[(size_t)NH * S * S], g_ps[(size_t)NH * S * S];  // 512 MB
__device__ bf16 g_ab[(size_t)S * HID], g_as[(size_t)S * HID];

// ---------------- asm helpers ----------------------------------------------
__device__ __forceinline__ void mma_bf16(float c[4],
    unsigned a0, unsigned a1, unsigned a2, unsigned a3, unsigned b0, unsigned b1)
{
    asm volatile(
        "mma.sync.aligned.m16n8k16.row.col.f32.bf16.bf16.f32 "
        "{%0,%1,%2,%3}, {%4,%5,%6,%7}, {%8,%9}, {%0,%1,%2,%3};"
        : "+f"(c[0]), "+f"(c[1]), "+f"(c[2]), "+f"(c[3])
        : "r"(a0), "r"(a1), "r"(a2), "r"(a3), "r"(b0), "r"(b1));
}

__device__ __forceinline__ void ldsm_x4(unsigned r[4], unsigned addr)
{
    asm volatile("ldmatrix.sync.aligned.m8n8.x4.shared.b16 {%0,%1,%2,%3}, [%4];"
        : "=r"(r[0]), "=r"(r[1]), "=r"(r[2]), "=r"(r[3]) : "r"(addr));
}
__device__ __forceinline__ void ldsm_x4t(unsigned r[4], unsigned addr)
{
    asm volatile("ldmatrix.sync.aligned.m8n8.x4.trans.shared.b16 {%0,%1,%2,%3}, [%4];"
        : "=r"(r[0]), "=r"(r[1]), "=r"(r[2]), "=r"(r[3]) : "r"(addr));
}
__device__ __forceinline__ void cp16(unsigned dst, const void* src)
{
    asm volatile("cp.async.cg.shared.global [%0], [%1], 16;" :: "r"(dst), "l"(src));
}
__device__ __forceinline__ void cp_commit() { asm volatile("cp.async.commit_group;" ::: "memory"); }
__device__ __forceinline__ void cp_wait1() { asm volatile("cp.async.wait_group 1;" ::: "memory"); }
__device__ __forceinline__ void cp_wait0() { asm volatile("cp.async.wait_group 0;" ::: "memory"); }

// ---------------- bf16x3 tensor-core GEMM, pre-split operands ---------------
// C = alpha * A @ op(B); A: [M,K] row-major bf16 (big+small arrays).
// NT=true : B [N,K] row-major; NT=false: B [K,N] row-major.
// EPI: 0 = fp32 store, 1 = fp32 + alpha + causal (tile skip), 2 = split bf16 store.
// TRUNC: cap K at bm+BM (causal PV).
#define BM 128
#define BN 128
#define BK 32
#define A_ST 20      // u32 row stride of A smem (16 pairs + 4 pad)
#define ASZ  (128 * A_ST)          // 2560 u32
#define BNT_ST 20
#define BNN_ST 68    // u32 row stride of NN B smem (64 + 4 pad)

template <bool NT, int EPI, bool TRUNC>
__global__ __launch_bounds__(256, 2) void gemm_bf3(
    const bf16* __restrict__ Agb, const bf16* __restrict__ Ags, int lda, size_t sA,
    const bf16* __restrict__ Bgb, const bf16* __restrict__ Bgs, int ldb, size_t sB,
    float* __restrict__ Cf, bf16* __restrict__ Cb, bf16* __restrict__ Cs,
    int ldc, size_t sC, int K, float alpha)
{
    const int bz = blockIdx.z;
    Agb += (size_t)bz * sA; Ags += (size_t)bz * sA;
    Bgb += (size_t)bz * sB; Bgs += (size_t)bz * sB;
    if (EPI == 2) { Cb += (size_t)bz * sC; Cs += (size_t)bz * sC; }
    else          { Cf += (size_t)bz * sC; }

    const int bm = blockIdx.y * BM, bn = blockIdx.x * BN;
    const int tid  = threadIdx.x;
    const int wid  = tid >> 5;
    const int lane = tid & 31;
    const int g  = lane >> 2;
    const int tg = lane & 3;
    const int wm = (wid & 3) * 32;
    const int wn = (wid >> 2) * 64;

    // fully-masked causal tile: fill NEG and exit
    if (EPI == 1 && bn > bm) {
#pragma unroll
        for (int mi = 0; mi < 2; mi++)
#pragma unroll
            for (int ni = 0; ni < 8; ni++) {
                int r0 = bm + wm + mi * 16 + g;
                int c0 = bn + wn + ni * 8 + tg * 2;
                *(float2*)(Cf + (size_t)r0 * ldc + c0)       = make_float2(NEGV, NEGV);
                *(float2*)(Cf + (size_t)(r0 + 8) * ldc + c0) = make_float2(NEGV, NEGV);
            }
        return;
    }

    extern __shared__ unsigned sm[];
    const unsigned smb = (unsigned)__cvta_generic_to_shared(sm);
    const int BSZ = NT ? (128 * BNT_ST) : (32 * BNN_ST);
    const int STG = 2 * ASZ + 2 * BSZ;   // u32 per stage
    const int OFF_AB = 0, OFF_AS = ASZ, OFF_BB = 2 * ASZ, OFF_BS = 2 * ASZ + BSZ;

    const int kend = TRUNC ? (bm + BM) : K;
    const int T = kend / BK;

    // ---- loader: 8 cp.async per thread per stage
    auto load_stage = [&](int t, int stage) {
        const int so = stage * STG;
        const int k0 = t * BK;
#pragma unroll
        for (int r = 0; r < 2; r++) {
            int s = tid + r * 256;
            // A: row s>>2, k-seg s&3 (8 bf16)
            int arow = s >> 2, aseg = s & 3;
            size_t aoff = (size_t)(bm + arow) * lda + k0 + aseg * 8;
            unsigned adst = smb + (so + OFF_AB + arow * A_ST + aseg * 4) * 4;
            cp16(adst, Agb + aoff);
            cp16(adst + ASZ * 4, Ags + aoff);
            if (NT) {
                size_t boff = (size_t)(bn + arow) * ldb + k0 + aseg * 8;
                unsigned bdst = smb + (so + OFF_BB + arow * BNT_ST + aseg * 4) * 4;
                cp16(bdst, Bgb + boff);
                cp16(bdst + BSZ * 4, Bgs + boff);
            } else {
                int krow = s >> 4, nseg = s & 15;
                size_t boff = (size_t)(k0 + krow) * ldb + bn + nseg * 8;
                unsigned bdst = smb + (so + OFF_BB + krow * BNN_ST + nseg * 4) * 4;
                cp16(bdst, Bgb + boff);
                cp16(bdst + BSZ * 4, Bgs + boff);
            }
        }
        cp_commit();
    };

    float acc[2][8][4];
#pragma unroll
    for (int i = 0; i < 2; i++)
#pragma unroll
        for (int j = 0; j < 8; j++)
#pragma unroll
            for (int t2 = 0; t2 < 4; t2++) acc[i][j][t2] = 0.f;

    // fragment smem addresses (stage-relative, bytes)
    const int a_row = (lane & 15);
    const int a_hi  = (lane >> 4) << 2;                  // +4 u32 for k8..15
    const int bnt_row = (lane & 7) + ((lane >> 4) & 1) * 8;
    const int bnt_hi  = ((lane >> 3) & 1) * 4;
    const int bnn_krow = (lane & 15);
    const int bnn_nhi  = ((lane >> 4) & 1) * 8;

    load_stage(0, 0);

    for (int t = 0; t < T; t++) {
        if (t + 1 < T) load_stage(t + 1, (t + 1) & 1);
        if (t + 1 < T) cp_wait1(); else cp_wait0();
        __syncthreads();

        const int so = (t & 1) * STG;
#pragma unroll
        for (int kk = 0; kk < 2; kk++) {
            unsigned ab[2][4], as_[2][4];
#pragma unroll
            for (int mi = 0; mi < 2; mi++) {
                int idx = (wm + mi * 16 + a_row) * A_ST + kk * 8 + a_hi;
                ldsm_x4(ab[mi],  smb + (so + OFF_AB + idx) * 4);
                ldsm_x4(as_[mi], smb + (so + OFF_AS + idx) * 4);
            }
#pragma unroll
            for (int nj = 0; nj < 4; nj++) {
                unsigned bb[4], bs[4];
                if (NT) {
                    int idx = (wn + nj * 16 + bnt_row) * BNT_ST + kk * 8 + bnt_hi;
                    ldsm_x4(bb, smb + (so + OFF_BB + idx) * 4);
                    ldsm_x4(bs, smb + (so + OFF_BS + idx) * 4);
                } else {
                    int idx = (kk * 16 + bnn_krow) * BNN_ST + ((wn + nj * 16 + bnn_nhi) >> 1);
                    ldsm_x4t(bb, smb + (so + OFF_BB + idx) * 4);
                    ldsm_x4t(bs, smb + (so + OFF_BS + idx) * 4);
                }
#pragma unroll
                for (int mi = 0; mi < 2; mi++) {
                    float* c0 = acc[mi][2 * nj];
                    float* c1 = acc[mi][2 * nj + 1];
                    mma_bf16(c0, ab[mi][0], ab[mi][1], ab[mi][2], ab[mi][3], bs[0], bs[1]);
                    mma_bf16(c0, as_[mi][0], as_[mi][1], as_[mi][2], as_[mi][3], bb[0], bb[1]);
                    mma_bf16(c0, ab[mi][0], ab[mi][1], ab[mi][2], ab[mi][3], bb[0], bb[1]);
                    mma_bf16(c1, ab[mi][0], ab[mi][1], ab[mi][2], ab[mi][3], bs[2], bs[3]);
                    mma_bf16(c1, as_[mi][0], as_[mi][1], as_[mi][2], as_[mi][3], bb[2], bb[3]);
                    mma_bf16(c1, ab[mi][0], ab[mi][1], ab[mi][2], ab[mi][3], bb[2], bb[3]);
                }
            }
        }
        __syncthreads();
    }

    // ---- epilogue
#pragma unroll
    for (int mi = 0; mi < 2; mi++) {
#pragma unroll
        for (int ni = 0; ni < 8; ni++) {
            int r0 = bm + wm + mi * 16 + g;
            int c0 = bn + wn + ni * 8 + tg * 2;
            float v0 = acc[mi][ni][0] * alpha;
            float v1 = acc[mi][ni][1] * alpha;
            float v2 = acc[mi][ni][2] * alpha;
            float v3 = acc[mi][ni][3] * alpha;
            if (EPI == 1) {
                if (c0     > r0)     v0 += NEGV;
                if (c0 + 1 > r0)     v1 += NEGV;
                if (c0     > r0 + 8) v2 += NEGV;
                if (c0 + 1 > r0 + 8) v3 += NEGV;
            }
            if (EPI == 2) {
                bf16 b0 = __float2bfloat16(v0), b1 = __float2bfloat16(v1);
                bf16 b2 = __float2bfloat16(v2), b3 = __float2bfloat16(v3);
                __nv_bfloat162 pb0 = {b0, b1}, pb1 = {b2, b3};
                __nv_bfloat162 ps0 = {__float2bfloat16(v0 - __bfloat162float(b0)),
                                      __float2bfloat16(v1 - __bfloat162float(b1))};
                __nv_bfloat162 ps1 = {__float2bfloat16(v2 - __bfloat162float(b2)),
                                      __float2bfloat16(v3 - __bfloat162float(b3))};
                *(__nv_bfloat162*)(Cb + (size_t)r0 * ldc + c0)       = pb0;
                *(__nv_bfloat162*)(Cb + (size_t)(r0 + 8) * ldc + c0) = pb1;
                *(__nv_bfloat162*)(Cs + (size_t)r0 * ldc + c0)       = ps0;
                *(__nv_bfloat162*)(Cs + (size_t)(r0 + 8) * ldc + c0) = ps1;
            } else {
                *(float2*)(Cf + (size_t)r0 * ldc + c0)       = make_float2(v0, v1);
                *(float2*)(Cf + (size_t)(r0 + 8) * ldc + c0) = make_float2(v2, v3);
            }
        }
    }
}

// ---------------- split fp32 -> bf16 big/small ------------------------------
__global__ void split_kernel(const float* __restrict__ x,
                             bf16* __restrict__ xb, bf16* __restrict__ xs)
{
    size_t i = ((size_t)blockIdx.x * 256 + threadIdx.x) * 4;
    float4 v = *(const float4*)(x + i);
    bf16 b0 = __float2bfloat16(v.x), b1 = __float2bfloat16(v.y);
    bf16 b2 = __float2bfloat16(v.z), b3 = __float2bfloat16(v.w);
    __nv_bfloat162 pb0 = {b0, b1}, pb1 = {b2, b3};
    __nv_bfloat162 ps0 = {__float2bfloat16(v.x - __bfloat162float(b0)),
                          __float2bfloat16(v.y - __bfloat162float(b1))};
    __nv_bfloat162 ps1 = {__float2bfloat16(v.z - __bfloat162float(b2)),
                          __float2bfloat16(v.w - __bfloat162float(b3))};
    *(__nv_bfloat162*)(xb + i)     = pb0;
    *(__nv_bfloat162*)(xb + i + 2) = pb1;
    *(__nv_bfloat162*)(xs + i)     = ps0;
    *(__nv_bfloat162*)(xs + i + 2) = ps1;
}

// ---------------- MsPoE rotary -> split bf16 --------------------------------
__global__ void rope_split_kernel(const float* __restrict__ q, const float* __restrict__ k,
                                  const int* __restrict__ pos_ids,
                                  bf16* __restrict__ qb, bf16* __restrict__ qs,
                                  bf16* __restrict__ kb, bf16* __restrict__ ks)
{
    int i = blockIdx.x * blockDim.x + threadIdx.x;
    int d = i & 63;
    int h = (i >> 6) & 31;
    int s = i >> 11;
    float ratio = 1.2f + (0.6f / 31.0f) * (float)h;
    float t = (float)pos_ids[s] / ratio;
    float inv_freq = exp2f(-(float)d * (13.287712379549449f / 64.0f));
    float f = t * inv_freq;
    float c, sn;
    sincosf(f, &sn, &c);
    size_t base = (size_t)s * HID + h * HD + d;

    float x1 = q[base], x2 = q[base + 64];
    float y0 = x1 * c - x2 * sn;
    float y1 = x2 * c + x1 * sn;
    bf16 t0 = __float2bfloat16(y0), t1 = __float2bfloat16(y1);
    qb[base] = t0;       qs[base]      = __float2bfloat16(y0 - __bfloat162float(t0));
    qb[base + 64] = t1;  qs[base + 64] = __float2bfloat16(y1 - __bfloat162float(t1));

    x1 = k[base]; x2 = k[base + 64];
    y0 = x1 * c - x2 * sn;
    y1 = x2 * c + x1 * sn;
    t0 = __float2bfloat16(y0); t1 = __float2bfloat16(y1);
    kb[base] = t0;       ks[base]      = __float2bfloat16(y0 - __bfloat162float(t0));
    kb[base + 64] = t1;  ks[base + 64] = __float2bfloat16(y1 - __bfloat162float(t1));
}

// ---------------- softmax pass 1: per-row max and 1/sum ---------------------
__global__ void rowstats_kernel(const float* __restrict__ scores,
                                float* __restrict__ rowmax, float* __restrict__ rsinv)
{
    int q = blockIdx.x, h = blockIdx.y;
    const float* row = scores + ((size_t)h * S + q) * S;
    __shared__ float red[256];
    int tid = threadIdx.x;

    float m = -INFINITY;
    for (int k = tid; k < S; k += 256) m = fmaxf(m, row[k]);
    red[tid] = m; __syncthreads();
    for (int st = 128; st; st >>= 1) {
        if (tid < st) red[tid] = fmaxf(red[tid], red[tid + st]);
        __syncthreads();
    }
    m = red[0];
    __syncthreads();

    float sum = 0.f;
    for (int k = tid; k < S; k += 256) sum += expf(row[k] - m);
    red[tid] = sum; __syncthreads();
    for (int st = 128; st; st >>= 1) {
        if (tid < st) red[tid] += red[tid + st];
        __syncthreads();
    }
    if (tid == 0) {
        rowmax[h * S + q] = m;
        rsinv[h * S + q]  = 1.0f / red[0];
    }
}

// ---------------- hh_score[h][k] = sum_q softmax(scores)[h][q][k] -----------
__global__ void hh_kernel(const float* __restrict__ scores,
                          const float* __restrict__ rowmax,
                          const float* __restrict__ rsinv, float* __restrict__ hh)
{
    int h = blockIdx.y;
    int k = blockIdx.x * 256 + threadIdx.x;
    const float* base = scores + (size_t)h * S * S;
    const float* rm = rowmax + h * S;
    const float* ri = rsinv + h * S;
    float acc = 0.f;
#pragma unroll 4
    for (int q = 0; q < S; q++) {
        acc += expf(base[(size_t)q * S + k] - rm[q]) * ri[q];
    }
    hh[h * S + k] = acc;
}

// ---------------- per-head top-204 over hh[:SEL]; build key mask ------------
__global__ void topk_mask_kernel(const float* __restrict__ hh, float* __restrict__ mask)
{
    int h = blockIdx.x;
    int tid = threadIdx.x;
    __shared__ float vals[SEL];
    __shared__ float rmax[256];
    __shared__ int   ridx[256];

    for (int i = tid; i < SEL; i += 256) vals[i] = hh[h * S + i];
    for (int k = tid; k < S; k += 256)  mask[h * S + k] = (k >= SEL) ? 0.f : NEGV;
    __syncthreads();

    for (int it = 0; it < HHSZ; it++) {
        float bm = -INFINITY; int bi = SEL;
        for (int i = tid; i < SEL; i += 256) {
            float v = vals[i];
            if (v > bm) { bm = v; bi = i; }
        }
        rmax[tid] = bm; ridx[tid] = bi;
        __syncthreads();
        for (int st = 128; st; st >>= 1) {
            if (tid < st) {
                if (rmax[tid + st] > rmax[tid] ||
                    (rmax[tid + st] == rmax[tid] && ridx[tid + st] < ridx[tid])) {
                    rmax[tid] = rmax[tid + st];
                    ridx[tid] = ridx[tid + st];
                }
            }
            __syncthreads();
        }
        if (tid == 0) {
            int kk = ridx[0];
            mask[h * S + kk] = 0.f;
            vals[kk] = -INFINITY;
        }
        __syncthreads();
    }
}

// ---------------- softmax pass 2 (masked), output split bf16 probs ----------
__global__ void softmax2_split_kernel(const float* __restrict__ scores,
                                      const float* __restrict__ mask,
                                      bf16* __restrict__ pb, bf16* __restrict__ ps)
{
    int q = blockIdx.x, h = blockIdx.y;
    const float* row = scores + ((size_t)h * S + q) * S;
    size_t off = ((size_t)h * S + q) * S;
    const float* mk = mask + h * S;
    __shared__ float red[256];
    int tid = threadIdx.x;

    float v[8];
    float m = -INFINITY;
#pragma unroll
    for (int j = 0; j < 8; j++) {
        int k = tid + j * 256;
        float x = row[k] + ((k == q) ? 0.f : mk[k]);
        v[j] = x;
        m = fmaxf(m, x);
    }
    red[tid] = m; __syncthreads();
    for (int st = 128; st; st >>= 1) {
        if (tid < st) red[tid] = fmaxf(red[tid], red[tid + st]);
        __syncthreads();
    }
    m = red[0];
    __syncthreads();

    float sum = 0.f;
#pragma unroll
    for (int j = 0; j < 8; j++) {
        v[j] = expf(v[j] - m);
        sum += v[j];
    }
    red[tid] = sum; __syncthreads();
    for (int st = 128; st; st >>= 1) {
        if (tid < st) red[tid] += red[tid + st];
        __syncthreads();
    }
    float inv = 1.0f / red[0];
#pragma unroll
    for (int j = 0; j < 8; j++) {
        int k = tid + j * 256;
        float val = v[j] * inv;
        bf16 b = __float2bfloat16(val);
        pb[off + k] = b;
        ps[off + k] = __float2bfloat16(val - __bfloat162float(b));
    }
}

// ---------------- launch -----------------------------------------------------
extern "C" void kernel_launch(void* const* d_in, const int* in_sizes, int n_in,
                              void* d_out, int out_size)
{
    const float* hs = (const float*)d_in[0];
    const float* W[4] = {(const float*)d_in[1], (const float*)d_in[2],
                         (const float*)d_in[3], (const float*)d_in[4]};
    const int* pos = (const int*)d_in[5];
    float* out = (float*)d_out;

    float *q, *k, *scores, *rmax, *rsinv, *hh, *mask;
    bf16 *hsb, *hss, *wb, *ws, *qb, *qs, *kb, *ks, *vb, *vs, *pb, *ps, *ab, *as;
    cudaGetSymbolAddress((void**)&q, g_q);
    cudaGetSymbolAddress((void**)&k, g_k);
    cudaGetSymbolAddress((void**)&scores, g_scores);
    cudaGetSymbolAddress((void**)&rmax, g_rowmax);
    cudaGetSymbolAddress((void**)&rsinv, g_rsinv);
    cudaGetSymbolAddress((void**)&hh, g_hh);
    cudaGetSymbolAddress((void**)&mask, g_mask);
    cudaGetSymbolAddress((void**)&hsb, g_hs_b);
    cudaGetSymbolAddress((void**)&hss, g_hs_s);
    cudaGetSymbolAddress((void**)&wb, g_w_b);
    cudaGetSymbolAddress((void**)&ws, g_w_s);
    cudaGetSymbolAddress((void**)&qb, g_qb);
    cudaGetSymbolAddress((void**)&qs, g_qs);
    cudaGetSymbolAddress((void**)&kb, g_kb);
    cudaGetSymbolAddress((void**)&ks, g_ks);
    cudaGetSymbolAddress((void**)&vb, g_vb);
    cudaGetSymbolAddress((void**)&vs, g_vs);
    cudaGetSymbolAddress((void**)&pb, g_pb);
    cudaGetSymbolAddress((void**)&ps, g_ps);
    cudaGetSymbolAddress((void**)&ab, g_ab);
    cudaGetSymbolAddress((void**)&as, g_as);

    const int SM_NT = (2 * (2 * ASZ + 2 * 128 * BNT_ST)) * 4;  // 81920 B
    const int SM_NN = (2 * (2 * ASZ + 2 * 32 * BNN_ST)) * 4;   // 75776 B
    cudaFuncSetAttribute(gemm_bf3<true, 0, false>, cudaFuncAttributeMaxDynamicSharedMemorySize, SM_NT);
    cudaFuncSetAttribute(gemm_bf3<true, 1, false>, cudaFuncAttributeMaxDynamicSharedMemorySize, SM_NT);
    cudaFuncSetAttribute(gemm_bf3<true, 2, false>, cudaFuncAttributeMaxDynamicSharedMemorySize, SM_NT);
    cudaFuncSetAttribute(gemm_bf3<false, 2, true>, cudaFuncAttributeMaxDynamicSharedMemorySize, SM_NN);

    dim3 blk(256);

    // split inputs once
    split_kernel<<<(S * HID) / 1024, 256>>>(hs, hsb, hss);
    for (int i = 0; i < 4; i++)
        split_kernel<<<(HID * (size_t)HID) / 1024, 256>>>(
            W[i], wb + (size_t)i * HID * HID, ws + (size_t)i * HID * HID);

    // projections
    dim3 gp(HID / BN, S / BM, 1);
    gemm_bf3<true, 0, false><<<gp, blk, SM_NT>>>(
        hsb, hss, HID, 0, wb + 0 * (size_t)HID * HID, ws + 0 * (size_t)HID * HID, HID, 0,
        q, nullptr, nullptr, HID, 0, HID, 1.f);
    gemm_bf3<true, 0, false><<<gp, blk, SM_NT>>>(
        hsb, hss, HID, 0, wb + 1 * (size_t)HID * HID, ws + 1 * (size_t)HID * HID, HID, 0,
        k, nullptr, nullptr, HID, 0, HID, 1.f);
    gemm_bf3<true, 2, false><<<gp, blk, SM_NT>>>(
        hsb, hss, HID, 0, wb + 2 * (size_t)HID * HID, ws + 2 * (size_t)HID * HID, HID, 0,
        nullptr, vb, vs, HID, 0, HID, 1.f);

    // rotary + split q/k
    rope_split_kernel<<<(S * NH * 64) / 256, 256>>>(q, k, pos, qb, qs, kb, ks);

    // scores = (q @ k^T)/sqrt(D) + causal, batched heads, upper tiles skipped
    dim3 gs(S / BN, S / BM, NH);
    gemm_bf3<true, 1, false><<<gs, blk, SM_NT>>>(
        qb, qs, HID, (size_t)HD, kb, ks, HID, (size_t)HD,
        scores, nullptr, nullptr, S, (size_t)S * S, HD, 0.08838834764831845f);

    // softmax1 stats + heavy-hitter scores + top-k mask
    rowstats_kernel<<<dim3(S, NH), 256>>>(scores, rmax, rsinv);
    hh_kernel<<<dim3(S / 256, NH), 256>>>(scores, rmax, rsinv, hh);
    topk_mask_kernel<<<NH, 256>>>(hh, mask);

    // masked softmax -> split bf16 probs
    softmax2_split_kernel<<<dim3(S, NH), 256>>>(scores, mask, pb, ps);

    // attn = probs @ v (NN, K truncated at diagonal), split bf16 out
    dim3 gpv(HD / BN, S / BM, NH);
    gemm_bf3<false, 2, true><<<gpv, blk, SM_NN>>>(
        pb, ps, S, (size_t)S * S, vb, vs, HID, (size_t)HD,
        nullptr, ab, as, HID, (size_t)HD, S, 1.f);

    // out = attn @ Wo^T
    gemm_bf3<true, 0, false><<<gp, blk, SM_NT>>>(
        ab, as, HID, 0, wb + 3 * (size_t)HID * HID, ws + 3 * (size_t)HID * HID, HID, 0,
        out, nullptr, nullptr, HID, 0, HID, 1.f);
}

// round 9
// speedup vs baseline: 2.5409x; 1.1056x over previous
#include <cuda_runtime.h>
#include <cuda_bf16.h>
#include <math.h>

#define S    2048
#define NH   32
#define HD   128
#define HID  4096
#define NEGV -1000000000.0f
#define HHSZ 204
#define RECENT 204
#define SEL  (S - RECENT)

typedef __nv_bfloat16 bf16;

// ---------------- scratch ----------------------------------------------------
__device__ float g_q[(size_t)S * HID];
__device__ float g_k[(size_t)S * HID];
__device__ float g_scores[(size_t)NH * S * S];
__device__ float g_hh[NH * S];
__device__ float g_mask[NH * S];

__device__ bf16 g_hs_b[(size_t)S * HID],  g_hs_s[(size_t)S * HID];
__device__ bf16 g_w_b[4][(size_t)HID * HID], g_w_s[4][(size_t)HID * HID];
__device__ bf16 g_qb[(size_t)S * HID], g_qs[(size_t)S * HID];
__device__ bf16 g_kb[(size_t)S * HID], g_ks[(size_t)S * HID];
__device__ bf16 g_vb[(size_t)S * HID], g_vs[(size_t)S * HID];
__device__ bf16 g_pb[(size_t)NH * S * S], g_ps[(size_t)NH * S * S];
__device__ bf16 g_ab[(size_t)S * HID], g_as[(size_t)S * HID];

// ---------------- HMMA helpers (R5-proven) -----------------------------------
__device__ __forceinline__ void mma_bf16(float c[4],
    unsigned a0, unsigned a1, unsigned a2, unsigned a3, unsigned b0, unsigned b1)
{
    asm volatile(
        "mma.sync.aligned.m16n8k16.row.col.f32.bf16.bf16.f32 "
        "{%0,%1,%2,%3}, {%4,%5,%6,%7}, {%8,%9}, {%0,%1,%2,%3};"
        : "+f"(c[0]), "+f"(c[1]), "+f"(c[2]), "+f"(c[3])
        : "r"(a0), "r"(a1), "r"(a2), "r"(a3), "r"(b0), "r"(b1));
}
__device__ __forceinline__ void ldsm_x4(unsigned r[4], unsigned addr)
{
    asm volatile("ldmatrix.sync.aligned.m8n8.x4.shared.b16 {%0,%1,%2,%3}, [%4];"
        : "=r"(r[0]), "=r"(r[1]), "=r"(r[2]), "=r"(r[3]) : "r"(addr));
}
__device__ __forceinline__ void ldsm_x4t(unsigned r[4], unsigned addr)
{
    asm volatile("ldmatrix.sync.aligned.m8n8.x4.trans.shared.b16 {%0,%1,%2,%3}, [%4];"
        : "=r"(r[0]), "=r"(r[1]), "=r"(r[2]), "=r"(r[3]) : "r"(addr));
}
__device__ __forceinline__ void cp16(unsigned dst, const void* src)
{
    asm volatile("cp.async.cg.shared.global [%0], [%1], 16;" :: "r"(dst), "l"(src));
}
__device__ __forceinline__ void cp_commit() { asm volatile("cp.async.commit_group;" ::: "memory"); }
__device__ __forceinline__ void cp_wait1() { asm volatile("cp.async.wait_group 1;" ::: "memory"); }
__device__ __forceinline__ void cp_wait0() { asm volatile("cp.async.wait_group 0;" ::: "memory"); }

// ================= HMMA bf16x3 GEMM ==========================================
#define BM 128
#define BN 128
#define BK 32
#define A_ST 20
#define ASZ  (128 * A_ST)
#define BNT_ST 20
#define BNN_ST 68

template <bool NT, int EPI, bool TRUNC, bool LOWER>
__global__ __launch_bounds__(256, 2) void gemm_bf3(
    const bf16* __restrict__ Agb, const bf16* __restrict__ Ags, int lda, size_t sA,
    const bf16* __restrict__ Bgb, const bf16* __restrict__ Bgs, int ldb, size_t sB,
    float* __restrict__ Cf, bf16* __restrict__ Cb, bf16* __restrict__ Cs,
    int ldc, size_t sC, int K, float alpha)
{
    const int bz = blockIdx.z;
    Agb += (size_t)bz * sA; Ags += (size_t)bz * sA;
    Bgb += (size_t)bz * sB; Bgs += (size_t)bz * sB;
    if (EPI == 2) { Cb += (size_t)bz * sC; Cs += (size_t)bz * sC; }
    else          { Cf += (size_t)bz * sC; }

    int bm, bn;
    if (LOWER) {
        int idx = blockIdx.x;
        int r = (int)((sqrtf(8.f * (float)idx + 1.f) - 1.f) * 0.5f);
        while ((r + 1) * (r + 2) / 2 <= idx) r++;
        while (r * (r + 1) / 2 > idx) r--;
        bm = r * BM;
        bn = (idx - r * (r + 1) / 2) * BN;
    } else {
        bm = blockIdx.y * BM;
        bn = blockIdx.x * BN;
    }

    const int tid  = threadIdx.x;
    const int wid  = tid >> 5;
    const int lane = tid & 31;
    const int g  = lane >> 2;
    const int tg = lane & 3;
    const int wm = (wid & 3) * 32;
    const int wn = (wid >> 2) * 64;

    extern __shared__ unsigned sm[];
    const unsigned smb = (unsigned)__cvta_generic_to_shared(sm);
    const int BSZ = NT ? (128 * BNT_ST) : (32 * BNN_ST);
    const int STG = 2 * ASZ + 2 * BSZ;
    const int OFF_AB = 0, OFF_AS = ASZ, OFF_BB = 2 * ASZ, OFF_BS = 2 * ASZ + BSZ;

    const int kend = TRUNC ? (bm + BM) : K;
    const int T = kend / BK;

    float acc[2][8][4];
#pragma unroll
    for (int i = 0; i < 2; i++)
#pragma unroll
        for (int j = 0; j < 8; j++)
#pragma unroll
            for (int t2 = 0; t2 < 4; t2++) acc[i][j][t2] = 0.f;

    const int a_row = (lane & 15);
    const int a_hi  = (lane >> 4) << 2;
    const int bnt_row = (lane & 7) + ((lane >> 4) & 1) * 8;
    const int bnt_hi  = ((lane >> 3) & 1) * 4;
    const int bnn_krow = (lane & 15);
    const int bnn_nhi  = ((lane >> 4) & 1) * 8;

    // stage 0 load
    {
        const int so = 0;
#pragma unroll
        for (int r = 0; r < 2; r++) {
            int s = tid + r * 256;
            int arow = s >> 2, aseg = s & 3;
            size_t aoff = (size_t)(bm + arow) * lda + aseg * 8;
            unsigned adst = smb + (so + OFF_AB + arow * A_ST + aseg * 4) * 4;
            cp16(adst, Agb + aoff);
            cp16(adst + ASZ * 4, Ags + aoff);
            if (NT) {
                size_t boff = (size_t)(bn + arow) * ldb + aseg * 8;
                unsigned bdst = smb + (so + OFF_BB + arow * BNT_ST + aseg * 4) * 4;
                cp16(bdst, Bgb + boff);
                cp16(bdst + BSZ * 4, Bgs + boff);
            } else {
                int krow = s >> 4, nseg = s & 15;
                size_t boff = (size_t)krow * ldb + bn + nseg * 8;
                unsigned bdst = smb + (so + OFF_BB + krow * BNN_ST + nseg * 4) * 4;
                cp16(bdst, Bgb + boff);
                cp16(bdst + BSZ * 4, Bgs + boff);
            }
        }
        cp_commit();
    }

    for (int t = 0; t < T; t++) {
        if (t + 1 < T) {
            const int so = ((t + 1) & 1) * STG;
            const int k0 = (t + 1) * BK;
#pragma unroll
            for (int r = 0; r < 2; r++) {
                int s = tid + r * 256;
                int arow = s >> 2, aseg = s & 3;
                size_t aoff = (size_t)(bm + arow) * lda + k0 + aseg * 8;
                unsigned adst = smb + (so + OFF_AB + arow * A_ST + aseg * 4) * 4;
                cp16(adst, Agb + aoff);
                cp16(adst + ASZ * 4, Ags + aoff);
                if (NT) {
                    size_t boff = (size_t)(bn + arow) * ldb + k0 + aseg * 8;
                    unsigned bdst = smb + (so + OFF_BB + arow * BNT_ST + aseg * 4) * 4;
                    cp16(bdst, Bgb + boff);
                    cp16(bdst + BSZ * 4, Bgs + boff);
                } else {
                    int krow = s >> 4, nseg = s & 15;
                    size_t boff = (size_t)(k0 + krow) * ldb + bn + nseg * 8;
                    unsigned bdst = smb + (so + OFF_BB + krow * BNN_ST + nseg * 4) * 4;
                    cp16(bdst, Bgb + boff);
                    cp16(bdst + BSZ * 4, Bgs + boff);
                }
            }
            cp_commit();
            cp_wait1();
        } else {
            cp_wait0();
        }
        __syncthreads();

        const int so = (t & 1) * STG;
#pragma unroll
        for (int kk = 0; kk < 2; kk++) {
            unsigned ab[2][4], as_[2][4];
#pragma unroll
            for (int mi = 0; mi < 2; mi++) {
                int idx = (wm + mi * 16 + a_row) * A_ST + kk * 8 + a_hi;
                ldsm_x4(ab[mi],  smb + (so + OFF_AB + idx) * 4);
                ldsm_x4(as_[mi], smb + (so + OFF_AS + idx) * 4);
            }
#pragma unroll
            for (int nj = 0; nj < 4; nj++) {
                unsigned bb[4], bs[4];
                if (NT) {
                    int idx = (wn + nj * 16 + bnt_row) * BNT_ST + kk * 8 + bnt_hi;
                    ldsm_x4(bb, smb + (so + OFF_BB + idx) * 4);
                    ldsm_x4(bs, smb + (so + OFF_BS + idx) * 4);
                } else {
                    int idx = (kk * 16 + bnn_krow) * BNN_ST + ((wn + nj * 16 + bnn_nhi) >> 1);
                    ldsm_x4t(bb, smb + (so + OFF_BB + idx) * 4);
                    ldsm_x4t(bs, smb + (so + OFF_BS + idx) * 4);
                }
#pragma unroll
                for (int mi = 0; mi < 2; mi++) {
                    float* c0 = acc[mi][2 * nj];
                    float* c1 = acc[mi][2 * nj + 1];
                    mma_bf16(c0, ab[mi][0], ab[mi][1], ab[mi][2], ab[mi][3], bs[0], bs[1]);
                    mma_bf16(c0, as_[mi][0], as_[mi][1], as_[mi][2], as_[mi][3], bb[0], bb[1]);
                    mma_bf16(c0, ab[mi][0], ab[mi][1], ab[mi][2], ab[mi][3], bb[0], bb[1]);
                    mma_bf16(c1, ab[mi][0], ab[mi][1], ab[mi][2], ab[mi][3], bs[2], bs[3]);
                    mma_bf16(c1, as_[mi][0], as_[mi][1], as_[mi][2], as_[mi][3], bb[2], bb[3]);
                    mma_bf16(c1, ab[mi][0], ab[mi][1], ab[mi][2], ab[mi][3], bb[2], bb[3]);
                }
            }
        }
        __syncthreads();
    }

#pragma unroll
    for (int mi = 0; mi < 2; mi++) {
#pragma unroll
        for (int ni = 0; ni < 8; ni++) {
            int r0 = bm + wm + mi * 16 + g;
            int c0 = bn + wn + ni * 8 + tg * 2;
            float v0 = acc[mi][ni][0] * alpha;
            float v1 = acc[mi][ni][1] * alpha;
            float v2 = acc[mi][ni][2] * alpha;
            float v3 = acc[mi][ni][3] * alpha;
            if (EPI == 2) {
                bf16 b0 = __float2bfloat16(v0), b1 = __float2bfloat16(v1);
                bf16 b2 = __float2bfloat16(v2), b3 = __float2bfloat16(v3);
                __nv_bfloat162 pb0, pb1, ps0, ps1;
                pb0.x = b0; pb0.y = b1; pb1.x = b2; pb1.y = b3;
                ps0.x = __float2bfloat16(v0 - __bfloat162float(b0));
                ps0.y = __float2bfloat16(v1 - __bfloat162float(b1));
                ps1.x = __float2bfloat16(v2 - __bfloat162float(b2));
                ps1.y = __float2bfloat16(v3 - __bfloat162float(b3));
                *(__nv_bfloat162*)(Cb + (size_t)r0 * ldc + c0)       = pb0;
                *(__nv_bfloat162*)(Cb + (size_t)(r0 + 8) * ldc + c0) = pb1;
                *(__nv_bfloat162*)(Cs + (size_t)r0 * ldc + c0)       = ps0;
                *(__nv_bfloat162*)(Cs + (size_t)(r0 + 8) * ldc + c0) = ps1;
            } else {
                *(float2*)(Cf + (size_t)r0 * ldc + c0)       = make_float2(v0, v1);
                *(float2*)(Cf + (size_t)(r0 + 8) * ldc + c0) = make_float2(v2, v3);
            }
        }
    }
}

// ---------------- split fp32 -> bf16 big/small -------------------------------
__global__ void split_kernel(const float* __restrict__ x,
                             bf16* __restrict__ xb, bf16* __restrict__ xs)
{
    size_t i = ((size_t)blockIdx.x * 256 + threadIdx.x) * 4;
    float4 v = *(const float4*)(x + i);
    bf16 b0 = __float2bfloat16(v.x), b1 = __float2bfloat16(v.y);
    bf16 b2 = __float2bfloat16(v.z), b3 = __float2bfloat16(v.w);
    __nv_bfloat162 pb0, pb1, ps0, ps1;
    pb0.x = b0; pb0.y = b1; pb1.x = b2; pb1.y = b3;
    ps0.x = __float2bfloat16(v.x - __bfloat162float(b0));
    ps0.y = __float2bfloat16(v.y - __bfloat162float(b1));
    ps1.x = __float2bfloat16(v.z - __bfloat162float(b2));
    ps1.y = __float2bfloat16(v.w - __bfloat162float(b3));
    *(__nv_bfloat162*)(xb + i)     = pb0;
    *(__nv_bfloat162*)(xb + i + 2) = pb1;
    *(__nv_bfloat162*)(xs + i)     = ps0;
    *(__nv_bfloat162*)(xs + i + 2) = ps1;
}

// ---------------- MsPoE rotary -> split bf16 ---------------------------------
__global__ void rope_split_kernel(const float* __restrict__ q, const float* __restrict__ k,
                                  const int* __restrict__ pos_ids,
                                  bf16* __restrict__ qb, bf16* __restrict__ qs,
                                  bf16* __restrict__ kb, bf16* __restrict__ ks)
{
    int i = blockIdx.x * blockDim.x + threadIdx.x;
    int d = i & 63;
    int h = (i >> 6) & 31;
    int s = i >> 11;
    float ratio = 1.2f + (0.6f / 31.0f) * (float)h;
    float t = (float)pos_ids[s] / ratio;
    float inv_freq = exp2f(-(float)d * (13.287712379549449f / 64.0f));
    float f = t * inv_freq;
    float c, sn;
    sincosf(f, &sn, &c);
    size_t base = (size_t)s * HID + h * HD + d;

    float x1 = q[base], x2 = q[base + 64];
    float y0 = x1 * c - x2 * sn;
    float y1 = x2 * c + x1 * sn;
    bf16 t0 = __float2bfloat16(y0);
    bf16 t1 = __float2bfloat16(y1);
    qb[base] = t0;
    qs[base] = __float2bfloat16(y0 - __bfloat162float(t0));
    qb[base + 64] = t1;
    qs[base + 64] = __float2bfloat16(y1 - __bfloat162float(t1));

    x1 = k[base]; x2 = k[base + 64];
    y0 = x1 * c - x2 * sn;
    y1 = x2 * c + x1 * sn;
    t0 = __float2bfloat16(y0);
    t1 = __float2bfloat16(y1);
    kb[base] = t0;
    ks[base] = __float2bfloat16(y0 - __bfloat162float(t0));
    kb[base + 64] = t1;
    ks[base + 64] = __float2bfloat16(y1 - __bfloat162float(t1));
}

// ---------------- probs1: in-place softmax over k<=q --------------------------
__global__ void probs1_kernel(float* __restrict__ scores)
{
    int q = blockIdx.x, h = blockIdx.y;
    float* row = scores + ((size_t)h * S + q) * S;
    __shared__ float red[256];
    int tid = threadIdx.x;

    float v[8];
    float m = -INFINITY;
#pragma unroll
    for (int j = 0; j < 8; j++) {
        int k = tid + j * 256;
        v[j] = (k <= q) ? row[k] : -INFINITY;
        m = fmaxf(m, v[j]);
    }
    red[tid] = m;
    __syncthreads();
    for (int st = 128; st; st >>= 1) {
        if (tid < st) red[tid] = fmaxf(red[tid], red[tid + st]);
        __syncthreads();
    }
    m = red[0];
    __syncthreads();

    float sum = 0.f;
#pragma unroll
    for (int j = 0; j < 8; j++) {
        v[j] = expf(v[j] - m);
        sum += v[j];
    }
    red[tid] = sum;
    __syncthreads();
    for (int st = 128; st; st >>= 1) {
        if (tid < st) red[tid] += red[tid + st];
        __syncthreads();
    }
    float inv = 1.0f / red[0];
#pragma unroll
    for (int j = 0; j < 8; j++) {
        int k = tid + j * 256;
        if (k <= q) row[k] = v[j] * inv;
    }
}

// ---------------- hh[h][k] = sum_{q>=k} probs1[h][q][k] -----------------------
__global__ void hh_kernel(const float* __restrict__ p1, float* __restrict__ hh)
{
    int h = blockIdx.y;
    int k = blockIdx.x * 256 + threadIdx.x;
    int q0 = blockIdx.x * 256;
    const float* base = p1 + (size_t)h * S * S;
    float acc = 0.f;
    for (int q = q0; q < S; q++) {
        float val = base[(size_t)q * S + k];
        acc += (q >= k) ? val : 0.0f;
    }
    hh[h * S + k] = acc;
}

// ---------------- per-head top-204 over hh[:SEL]; build key mask --------------
__global__ void topk_mask_kernel(const float* __restrict__ hh, float* __restrict__ mask)
{
    int h = blockIdx.x;
    int tid = threadIdx.x;
    __shared__ float vals[SEL];
    __shared__ float rmax[256];
    __shared__ int   ridx[256];

    for (int i = tid; i < SEL; i += 256) vals[i] = hh[h * S + i];
    for (int k = tid; k < S; k += 256)  mask[h * S + k] = (k >= SEL) ? 0.f : NEGV;
    __syncthreads();

    for (int it = 0; it < HHSZ; it++) {
        float bm = -INFINITY;
        int bi = SEL;
        for (int i = tid; i < SEL; i += 256) {
            float v = vals[i];
            if (v > bm) { bm = v; bi = i; }
        }
        rmax[tid] = bm;
        ridx[tid] = bi;
        __syncthreads();
        for (int st = 128; st; st >>= 1) {
            if (tid < st) {
                if (rmax[tid + st] > rmax[tid] ||
                    (rmax[tid + st] == rmax[tid] && ridx[tid + st] < ridx[tid])) {
                    rmax[tid] = rmax[tid + st];
                    ridx[tid] = ridx[tid + st];
                }
            }
            __syncthreads();
        }
        if (tid == 0) {
            int kk = ridx[0];
            mask[h * S + kk] = 0.f;
            vals[kk] = -INFINITY;
        }
        __syncthreads();
    }
}

// ---------------- softmax2 = renormalize kept probs1; split bf16 out ----------
__global__ void softmax2_renorm_kernel(const float* __restrict__ p1,
                                       const float* __restrict__ mask,
                                       bf16* __restrict__ pb, bf16* __restrict__ ps)
{
    int q = blockIdx.x, h = blockIdx.y;
    size_t off = ((size_t)h * S + q) * S;
    const float* row = p1 + off;
    const float* mk = mask + h * S;
    __shared__ float red[256];
    int tid = threadIdx.x;
    int tend = ((q >> 7) + 1) << 7;

    float v[8];
    float sum = 0.f;
#pragma unroll
    for (int j = 0; j < 8; j++) {
        int k = tid + j * 256;
        bool kept = (k <= q) && ((mk[k] == 0.f) || (k == q));
        v[j] = kept ? row[k] : 0.f;
        sum += v[j];
    }
    red[tid] = sum;
    __syncthreads();
    for (int st = 128; st; st >>= 1) {
        if (tid < st) red[tid] += red[tid + st];
        __syncthreads();
    }
    float inv = 1.0f / red[0];
#pragma unroll
    for (int j = 0; j < 8; j++) {
        int k = tid + j * 256;
        if (k < tend) {
            float val = v[j] * inv;
            bf16 b = __float2bfloat16(val);
            pb[off + k] = b;
            ps[off + k] = __float2bfloat16(val - __bfloat162float(b));
        }
    }
}

// ---------------- launch -------------------------------------------------------
extern "C" void kernel_launch(void* const* d_in, const int* in_sizes, int n_in,
                              void* d_out, int out_size)
{
    const float* hs = (const float*)d_in[0];
    const float* W0 = (const float*)d_in[1];
    const float* W1 = (const float*)d_in[2];
    const float* W2 = (const float*)d_in[3];
    const float* W3 = (const float*)d_in[4];
    const int* pos = (const int*)d_in[5];
    float* out = (float*)d_out;

    float *q, *k, *scores, *hh, *mask;
    bf16 *hsb, *hss, *wb, *ws, *qb, *qs, *kb, *ks, *vb, *vs, *pb, *ps, *ab, *as;
    cudaGetSymbolAddress((void**)&q, g_q);
    cudaGetSymbolAddress((void**)&k, g_k);
    cudaGetSymbolAddress((void**)&scores, g_scores);
    cudaGetSymbolAddress((void**)&hh, g_hh);
    cudaGetSymbolAddress((void**)&mask, g_mask);
    cudaGetSymbolAddress((void**)&hsb, g_hs_b);
    cudaGetSymbolAddress((void**)&hss, g_hs_s);
    cudaGetSymbolAddress((void**)&wb, g_w_b);
    cudaGetSymbolAddress((void**)&ws, g_w_s);
    cudaGetSymbolAddress((void**)&qb, g_qb);
    cudaGetSymbolAddress((void**)&qs, g_qs);
    cudaGetSymbolAddress((void**)&kb, g_kb);
    cudaGetSymbolAddress((void**)&ks, g_ks);
    cudaGetSymbolAddress((void**)&vb, g_vb);
    cudaGetSymbolAddress((void**)&vs, g_vs);
    cudaGetSymbolAddress((void**)&pb, g_pb);
    cudaGetSymbolAddress((void**)&ps, g_ps);
    cudaGetSymbolAddress((void**)&ab, g_ab);
    cudaGetSymbolAddress((void**)&as, g_as);

    const int SM_NT = (2 * (2 * ASZ + 2 * 128 * BNT_ST)) * 4;
    const int SM_NN = (2 * (2 * ASZ + 2 * 32 * BNN_ST)) * 4;
    cudaFuncSetAttribute(gemm_bf3<true, 0, false, false>, cudaFuncAttributeMaxDynamicSharedMemorySize, SM_NT);
    cudaFuncSetAttribute(gemm_bf3<true, 2, false, false>, cudaFuncAttributeMaxDynamicSharedMemorySize, SM_NT);
    cudaFuncSetAttribute(gemm_bf3<true, 0, false, true>,  cudaFuncAttributeMaxDynamicSharedMemorySize, SM_NT);
    cudaFuncSetAttribute(gemm_bf3<false, 2, true, false>, cudaFuncAttributeMaxDynamicSharedMemorySize, SM_NN);

    dim3 blk(256);

    split_kernel<<<(S * HID) / 1024, 256>>>(hs, hsb, hss);
    split_kernel<<<(HID * HID) / 1024, 256>>>(W0, wb + 0 * (size_t)HID * HID, ws + 0 * (size_t)HID * HID);
    split_kernel<<<(HID * HID) / 1024, 256>>>(W1, wb + 1 * (size_t)HID * HID, ws + 1 * (size_t)HID * HID);
    split_kernel<<<(HID * HID) / 1024, 256>>>(W2, wb + 2 * (size_t)HID * HID, ws + 2 * (size_t)HID * HID);
    split_kernel<<<(HID * HID) / 1024, 256>>>(W3, wb + 3 * (size_t)HID * HID, ws + 3 * (size_t)HID * HID);

    // projections (HMMA bf16x3)
    dim3 gp(HID / BN, S / BM, 1);
    gemm_bf3<true, 0, false, false><<<gp, blk, SM_NT>>>(
        hsb, hss, HID, 0, wb + 0 * (size_t)HID * HID, ws + 0 * (size_t)HID * HID, HID, 0,
        q, (bf16*)0, (bf16*)0, HID, 0, HID, 1.f);
    gemm_bf3<true, 0, false, false><<<gp, blk, SM_NT>>>(
        hsb, hss, HID, 0, wb + 1 * (size_t)HID * HID, ws + 1 * (size_t)HID * HID, HID, 0,
        k, (bf16*)0, (bf16*)0, HID, 0, HID, 1.f);
    gemm_bf3<true, 2, false, false><<<gp, blk, SM_NT>>>(
        hsb, hss, HID, 0, wb + 2 * (size_t)HID * HID, ws + 2 * (size_t)HID * HID, HID, 0,
        (float*)0, vb, vs, HID, 0, HID, 1.f);

    rope_split_kernel<<<(S * NH * 64) / 256, 256>>>(q, k, pos, qb, qs, kb, ks);

    // QK^T lower-triangle tiles only
    dim3 gs(136, 1, NH);
    gemm_bf3<true, 0, false, true><<<gs, blk, SM_NT>>>(
        qb, qs, HID, (size_t)HD, kb, ks, HID, (size_t)HD,
        scores, (bf16*)0, (bf16*)0, S, (size_t)S * S, HD, 0.08838834764831845f);

    probs1_kernel<<<dim3(S, NH), 256>>>(scores);
    hh_kernel<<<dim3(S / 256, NH), 256>>>(scores, hh);
    topk_mask_kernel<<<NH, 256>>>(hh, mask);
    softmax2_renorm_kernel<<<dim3(S, NH), 256>>>(scores, mask, pb, ps);

    // PV (K truncated at diagonal)
    dim3 gpv(HD / BN, S / BM, NH);
    gemm_bf3<false, 2, true, false><<<gpv, blk, SM_NN>>>(
        pb, ps, S, (size_t)S * S, vb, vs, HID, (size_t)HD,
        (float*)0, ab, as, HID, (size_t)HD, S, 1.f);

    // O projection
    gemm_bf3<true, 0, false, false><<<gp, blk, SM_NT>>>(
        ab, as, HID, 0, wb + 3 * (size_t)HID * HID, ws + 3 * (size_t)HID * HID, HID, 0,
        out, (bf16*)0, (bf16*)0, HID, 0, HID, 1.f);
}

// round 10
// speedup vs baseline: 2.5576x; 1.0066x over previous
#include <cuda_runtime.h>
#include <cuda_bf16.h>
#include <math.h>

#define S    2048
#define NH   32
#define HD   128
#define HID  4096
#define NEGV -1000000000.0f
#define HHSZ 204
#define RECENT 204
#define SEL  (S - RECENT)

typedef __nv_bfloat16 bf16;

// ---------------- scratch ----------------------------------------------------
__device__ float g_q[(size_t)S * HID];
__device__ float g_k[(size_t)S * HID];
__device__ float g_scores[(size_t)NH * S * S];
__device__ float g_hh[NH * S];
__device__ float g_hhpart[8 * NH * S];
__device__ float g_mask[NH * S];

__device__ bf16 g_hs_b[(size_t)S * HID],  g_hs_s[(size_t)S * HID];
__device__ bf16 g_w_b[4][(size_t)HID * HID], g_w_s[4][(size_t)HID * HID];
__device__ bf16 g_qb[(size_t)S * HID], g_qs[(size_t)S * HID];
__device__ bf16 g_kb[(size_t)S * HID], g_ks[(size_t)S * HID];
__device__ bf16 g_vb[(size_t)S * HID], g_vs[(size_t)S * HID];
__device__ bf16 g_pb[(size_t)NH * S * S], g_ps[(size_t)NH * S * S];
__device__ bf16 g_ab[(size_t)S * HID], g_as[(size_t)S * HID];

// ---------------- HMMA helpers (proven) --------------------------------------
__device__ __forceinline__ void mma_bf16(float c[4],
    unsigned a0, unsigned a1, unsigned a2, unsigned a3, unsigned b0, unsigned b1)
{
    asm volatile(
        "mma.sync.aligned.m16n8k16.row.col.f32.bf16.bf16.f32 "
        "{%0,%1,%2,%3}, {%4,%5,%6,%7}, {%8,%9}, {%0,%1,%2,%3};"
        : "+f"(c[0]), "+f"(c[1]), "+f"(c[2]), "+f"(c[3])
        : "r"(a0), "r"(a1), "r"(a2), "r"(a3), "r"(b0), "r"(b1));
}
__device__ __forceinline__ void ldsm_x4(unsigned r[4], unsigned addr)
{
    asm volatile("ldmatrix.sync.aligned.m8n8.x4.shared.b16 {%0,%1,%2,%3}, [%4];"
        : "=r"(r[0]), "=r"(r[1]), "=r"(r[2]), "=r"(r[3]) : "r"(addr));
}
__device__ __forceinline__ void ldsm_x4t(unsigned r[4], unsigned addr)
{
    asm volatile("ldmatrix.sync.aligned.m8n8.x4.trans.shared.b16 {%0,%1,%2,%3}, [%4];"
        : "=r"(r[0]), "=r"(r[1]), "=r"(r[2]), "=r"(r[3]) : "r"(addr));
}
__device__ __forceinline__ void cp16(unsigned dst, const void* src)
{
    asm volatile("cp.async.cg.shared.global [%0], [%1], 16;" :: "r"(dst), "l"(src));
}
__device__ __forceinline__ void cp_commit() { asm volatile("cp.async.commit_group;" ::: "memory"); }
__device__ __forceinline__ void cp_wait1() { asm volatile("cp.async.wait_group 1;" ::: "memory"); }
__device__ __forceinline__ void cp_wait0() { asm volatile("cp.async.wait_group 0;" ::: "memory"); }

// ================= big-M HMMA GEMM: 256x128 tile, 512 threads, NT ============
// C[256-block, 128-block] = A[M,K] @ B[N,K]^T, bf16 3-term split.
// EPI 0: fp32 store; EPI 2: split bf16 store.
#define GB_AST 20
#define GB_ASZ (256 * GB_AST)     // 5120 u32
#define GB_BSZ (128 * GB_AST)     // 2560 u32
#define GB_STG (2 * GB_ASZ + 2 * GB_BSZ)   // 15360 u32
#define GB_SMEM (2 * GB_STG * 4)           // 122880 B

template <int EPI>
__global__ __launch_bounds__(512, 1) void gemm_big(
    const bf16* __restrict__ Agb, const bf16* __restrict__ Ags, int lda,
    const bf16* __restrict__ Bgb, const bf16* __restrict__ Bgs, int ldb,
    float* __restrict__ Cf, bf16* __restrict__ Cb, bf16* __restrict__ Cs,
    int ldc, int K)
{
    const int bm = blockIdx.y * 256;
    const int bn = blockIdx.x * 128;
    const int tid  = threadIdx.x;
    const int wid  = tid >> 5;
    const int lane = tid & 31;
    const int g  = lane >> 2;
    const int tg = lane & 3;
    const int wm = (wid & 7) * 32;
    const int wn = (wid >> 3) * 64;

    extern __shared__ unsigned sm[];
    const unsigned smb = (unsigned)__cvta_generic_to_shared(sm);
    const int OFF_AB = 0, OFF_AS = GB_ASZ, OFF_BB = 2 * GB_ASZ, OFF_BS = 2 * GB_ASZ + GB_BSZ;

    const int T = K / 32;

    float acc[2][8][4];
#pragma unroll
    for (int i = 0; i < 2; i++)
#pragma unroll
        for (int j = 0; j < 8; j++)
#pragma unroll
            for (int t2 = 0; t2 < 4; t2++) acc[i][j][t2] = 0.f;

    const int a_row = (lane & 15);
    const int a_hi  = (lane >> 4) << 2;
    const int bnt_row = (lane & 7) + ((lane >> 4) & 1) * 8;
    const int bnt_hi  = ((lane >> 3) & 1) * 4;

    // stage 0 load
    {
        const int so = 0;
#pragma unroll
        for (int r = 0; r < 2; r++) {
            int s = tid + r * 512;
            int arow = s >> 2, aseg = s & 3;
            size_t aoff = (size_t)(bm + arow) * lda + aseg * 8;
            unsigned adst = smb + (so + OFF_AB + arow * GB_AST + aseg * 4) * 4;
            cp16(adst, Agb + aoff);
            cp16(adst + GB_ASZ * 4, Ags + aoff);
        }
        int brow = tid >> 2, bseg = tid & 3;
        size_t boff = (size_t)(bn + brow) * ldb + bseg * 8;
        unsigned bdst = smb + (so + OFF_BB + brow * GB_AST + bseg * 4) * 4;
        cp16(bdst, Bgb + boff);
        cp16(bdst + GB_BSZ * 4, Bgs + boff);
        cp_commit();
    }

    for (int t = 0; t < T; t++) {
        if (t + 1 < T) {
            const int so = ((t + 1) & 1) * GB_STG;
            const int k0 = (t + 1) * 32;
#pragma unroll
            for (int r = 0; r < 2; r++) {
                int s = tid + r * 512;
                int arow = s >> 2, aseg = s & 3;
                size_t aoff = (size_t)(bm + arow) * lda + k0 + aseg * 8;
                unsigned adst = smb + (so + OFF_AB + arow * GB_AST + aseg * 4) * 4;
                cp16(adst, Agb + aoff);
                cp16(adst + GB_ASZ * 4, Ags + aoff);
            }
            int brow = tid >> 2, bseg = tid & 3;
            size_t boff = (size_t)(bn + brow) * ldb + k0 + bseg * 8;
            unsigned bdst = smb + (so + OFF_BB + brow * GB_AST + bseg * 4) * 4;
            cp16(bdst, Bgb + boff);
            cp16(bdst + GB_BSZ * 4, Bgs + boff);
            cp_commit();
            cp_wait1();
        } else {
            cp_wait0();
        }
        __syncthreads();

        const int so = (t & 1) * GB_STG;
#pragma unroll
        for (int kk = 0; kk < 2; kk++) {
            unsigned ab[2][4], as_[2][4];
#pragma unroll
            for (int mi = 0; mi < 2; mi++) {
                int idx = (wm + mi * 16 + a_row) * GB_AST + kk * 8 + a_hi;
                ldsm_x4(ab[mi],  smb + (so + OFF_AB + idx) * 4);
                ldsm_x4(as_[mi], smb + (so + OFF_AS + idx) * 4);
            }
#pragma unroll
            for (int nj = 0; nj < 4; nj++) {
                unsigned bb[4], bs[4];
                int idx = (wn + nj * 16 + bnt_row) * GB_AST + kk * 8 + bnt_hi;
                ldsm_x4(bb, smb + (so + OFF_BB + idx) * 4);
                ldsm_x4(bs, smb + (so + OFF_BS + idx) * 4);
#pragma unroll
                for (int mi = 0; mi < 2; mi++) {
                    float* c0 = acc[mi][2 * nj];
                    float* c1 = acc[mi][2 * nj + 1];
                    mma_bf16(c0, ab[mi][0], ab[mi][1], ab[mi][2], ab[mi][3], bs[0], bs[1]);
                    mma_bf16(c0, as_[mi][0], as_[mi][1], as_[mi][2], as_[mi][3], bb[0], bb[1]);
                    mma_bf16(c0, ab[mi][0], ab[mi][1], ab[mi][2], ab[mi][3], bb[0], bb[1]);
                    mma_bf16(c1, ab[mi][0], ab[mi][1], ab[mi][2], ab[mi][3], bs[2], bs[3]);
                    mma_bf16(c1, as_[mi][0], as_[mi][1], as_[mi][2], as_[mi][3], bb[2], bb[3]);
                    mma_bf16(c1, ab[mi][0], ab[mi][1], ab[mi][2], ab[mi][3], bb[2], bb[3]);
                }
            }
        }
        __syncthreads();
    }

#pragma unroll
    for (int mi = 0; mi < 2; mi++) {
#pragma unroll
        for (int ni = 0; ni < 8; ni++) {
            int r0 = bm + wm + mi * 16 + g;
            int c0 = bn + wn + ni * 8 + tg * 2;
            float v0 = acc[mi][ni][0];
            float v1 = acc[mi][ni][1];
            float v2 = acc[mi][ni][2];
            float v3 = acc[mi][ni][3];
            if (EPI == 2) {
                bf16 b0 = __float2bfloat16(v0), b1 = __float2bfloat16(v1);
                bf16 b2 = __float2bfloat16(v2), b3 = __float2bfloat16(v3);
                __nv_bfloat162 pb0, pb1, ps0, ps1;
                pb0.x = b0; pb0.y = b1; pb1.x = b2; pb1.y = b3;
                ps0.x = __float2bfloat16(v0 - __bfloat162float(b0));
                ps0.y = __float2bfloat16(v1 - __bfloat162float(b1));
                ps1.x = __float2bfloat16(v2 - __bfloat162float(b2));
                ps1.y = __float2bfloat16(v3 - __bfloat162float(b3));
                *(__nv_bfloat162*)(Cb + (size_t)r0 * ldc + c0)       = pb0;
                *(__nv_bfloat162*)(Cb + (size_t)(r0 + 8) * ldc + c0) = pb1;
                *(__nv_bfloat162*)(Cs + (size_t)r0 * ldc + c0)       = ps0;
                *(__nv_bfloat162*)(Cs + (size_t)(r0 + 8) * ldc + c0) = ps1;
            } else {
                *(float2*)(Cf + (size_t)r0 * ldc + c0)       = make_float2(v0, v1);
                *(float2*)(Cf + (size_t)(r0 + 8) * ldc + c0) = make_float2(v2, v3);
            }
        }
    }
}

// ================= HMMA bf16x3 GEMM 128x128 (QK lower-tri / PV) ==============
#define BM 128
#define BN 128
#define BK 32
#define A_ST 20
#define ASZ  (128 * A_ST)
#define BNT_ST 20
#define BNN_ST 68

template <bool NT, int EPI, bool TRUNC, bool LOWER>
__global__ __launch_bounds__(256, 2) void gemm_bf3(
    const bf16* __restrict__ Agb, const bf16* __restrict__ Ags, int lda, size_t sA,
    const bf16* __restrict__ Bgb, const bf16* __restrict__ Bgs, int ldb, size_t sB,
    float* __restrict__ Cf, bf16* __restrict__ Cb, bf16* __restrict__ Cs,
    int ldc, size_t sC, int K, float alpha)
{
    const int bz = blockIdx.z;
    Agb += (size_t)bz * sA; Ags += (size_t)bz * sA;
    Bgb += (size_t)bz * sB; Bgs += (size_t)bz * sB;
    if (EPI == 2) { Cb += (size_t)bz * sC; Cs += (size_t)bz * sC; }
    else          { Cf += (size_t)bz * sC; }

    int bm, bn;
    if (LOWER) {
        int idx = blockIdx.x;
        int r = (int)((sqrtf(8.f * (float)idx + 1.f) - 1.f) * 0.5f);
        while ((r + 1) * (r + 2) / 2 <= idx) r++;
        while (r * (r + 1) / 2 > idx) r--;
        bm = r * BM;
        bn = (idx - r * (r + 1) / 2) * BN;
    } else if (TRUNC) {
        bm = (gridDim.y - 1 - blockIdx.y) * BM;   // heavy tiles first
        bn = blockIdx.x * BN;
    } else {
        bm = blockIdx.y * BM;
        bn = blockIdx.x * BN;
    }

    const int tid  = threadIdx.x;
    const int wid  = tid >> 5;
    const int lane = tid & 31;
    const int g  = lane >> 2;
    const int tg = lane & 3;
    const int wm = (wid & 3) * 32;
    const int wn = (wid >> 2) * 64;

    extern __shared__ unsigned sm[];
    const unsigned smb = (unsigned)__cvta_generic_to_shared(sm);
    const int BSZ = NT ? (128 * BNT_ST) : (32 * BNN_ST);
    const int STG = 2 * ASZ + 2 * BSZ;
    const int OFF_AB = 0, OFF_AS = ASZ, OFF_BB = 2 * ASZ, OFF_BS = 2 * ASZ + BSZ;

    const int kend = TRUNC ? (bm + BM) : K;
    const int T = kend / BK;

    float acc[2][8][4];
#pragma unroll
    for (int i = 0; i < 2; i++)
#pragma unroll
        for (int j = 0; j < 8; j++)
#pragma unroll
            for (int t2 = 0; t2 < 4; t2++) acc[i][j][t2] = 0.f;

    const int a_row = (lane & 15);
    const int a_hi  = (lane >> 4) << 2;
    const int bnt_row = (lane & 7) + ((lane >> 4) & 1) * 8;
    const int bnt_hi  = ((lane >> 3) & 1) * 4;
    const int bnn_krow = (lane & 15);
    const int bnn_nhi  = ((lane >> 4) & 1) * 8;

    // stage 0 load
    {
        const int so = 0;
#pragma unroll
        for (int r = 0; r < 2; r++) {
            int s = tid + r * 256;
            int arow = s >> 2, aseg = s & 3;
            size_t aoff = (size_t)(bm + arow) * lda + aseg * 8;
            unsigned adst = smb + (so + OFF_AB + arow * A_ST + aseg * 4) * 4;
            cp16(adst, Agb + aoff);
            cp16(adst + ASZ * 4, Ags + aoff);
            if (NT) {
                size_t boff = (size_t)(bn + arow) * ldb + aseg * 8;
                unsigned bdst = smb + (so + OFF_BB + arow * BNT_ST + aseg * 4) * 4;
                cp16(bdst, Bgb + boff);
                cp16(bdst + BSZ * 4, Bgs + boff);
            } else {
                int krow = s >> 4, nseg = s & 15;
                size_t boff = (size_t)krow * ldb + bn + nseg * 8;
                unsigned bdst = smb + (so + OFF_BB + krow * BNN_ST + nseg * 4) * 4;
                cp16(bdst, Bgb + boff);
                cp16(bdst + BSZ * 4, Bgs + boff);
            }
        }
        cp_commit();
    }

    for (int t = 0; t < T; t++) {
        if (t + 1 < T) {
            const int so = ((t + 1) & 1) * STG;
            const int k0 = (t + 1) * BK;
#pragma unroll
            for (int r = 0; r < 2; r++) {
                int s = tid + r * 256;
                int arow = s >> 2, aseg = s & 3;
                size_t aoff = (size_t)(bm + arow) * lda + k0 + aseg * 8;
                unsigned adst = smb + (so + OFF_AB + arow * A_ST + aseg * 4) * 4;
                cp16(adst, Agb + aoff);
                cp16(adst + ASZ * 4, Ags + aoff);
                if (NT) {
                    size_t boff = (size_t)(bn + arow) * ldb + k0 + aseg * 8;
                    unsigned bdst = smb + (so + OFF_BB + arow * BNT_ST + aseg * 4) * 4;
                    cp16(bdst, Bgb + boff);
                    cp16(bdst + BSZ * 4, Bgs + boff);
                } else {
                    int krow = s >> 4, nseg = s & 15;
                    size_t boff = (size_t)(k0 + krow) * ldb + bn + nseg * 8;
                    unsigned bdst = smb + (so + OFF_BB + krow * BNN_ST + nseg * 4) * 4;
                    cp16(bdst, Bgb + boff);
                    cp16(bdst + BSZ * 4, Bgs + boff);
                }
            }
            cp_commit();
            cp_wait1();
        } else {
            cp_wait0();
        }
        __syncthreads();

        const int so = (t & 1) * STG;
#pragma unroll
        for (int kk = 0; kk < 2; kk++) {
            unsigned ab[2][4], as_[2][4];
#pragma unroll
            for (int mi = 0; mi < 2; mi++) {
                int idx = (wm + mi * 16 + a_row) * A_ST + kk * 8 + a_hi;
                ldsm_x4(ab[mi],  smb + (so + OFF_AB + idx) * 4);
                ldsm_x4(as_[mi], smb + (so + OFF_AS + idx) * 4);
            }
#pragma unroll
            for (int nj = 0; nj < 4; nj++) {
                unsigned bb[4], bs[4];
                if (NT) {
                    int idx = (wn + nj * 16 + bnt_row) * BNT_ST + kk * 8 + bnt_hi;
                    ldsm_x4(bb, smb + (so + OFF_BB + idx) * 4);
                    ldsm_x4(bs, smb + (so + OFF_BS + idx) * 4);
                } else {
                    int idx = (kk * 16 + bnn_krow) * BNN_ST + ((wn + nj * 16 + bnn_nhi) >> 1);
                    ldsm_x4t(bb, smb + (so + OFF_BB + idx) * 4);
                    ldsm_x4t(bs, smb + (so + OFF_BS + idx) * 4);
                }
#pragma unroll
                for (int mi = 0; mi < 2; mi++) {
                    float* c0 = acc[mi][2 * nj];
                    float* c1 = acc[mi][2 * nj + 1];
                    mma_bf16(c0, ab[mi][0], ab[mi][1], ab[mi][2], ab[mi][3], bs[0], bs[1]);
                    mma_bf16(c0, as_[mi][0], as_[mi][1], as_[mi][2], as_[mi][3], bb[0], bb[1]);
                    mma_bf16(c0, ab[mi][0], ab[mi][1], ab[mi][2], ab[mi][3], bb[0], bb[1]);
                    mma_bf16(c1, ab[mi][0], ab[mi][1], ab[mi][2], ab[mi][3], bs[2], bs[3]);
                    mma_bf16(c1, as_[mi][0], as_[mi][1], as_[mi][2], as_[mi][3], bb[2], bb[3]);
                    mma_bf16(c1, ab[mi][0], ab[mi][1], ab[mi][2], ab[mi][3], bb[2], bb[3]);
                }
            }
        }
        __syncthreads();
    }

#pragma unroll
    for (int mi = 0; mi < 2; mi++) {
#pragma unroll
        for (int ni = 0; ni < 8; ni++) {
            int r0 = bm + wm + mi * 16 + g;
            int c0 = bn + wn + ni * 8 + tg * 2;
            float v0 = acc[mi][ni][0] * alpha;
            float v1 = acc[mi][ni][1] * alpha;
            float v2 = acc[mi][ni][2] * alpha;
            float v3 = acc[mi][ni][3] * alpha;
            if (EPI == 2) {
                bf16 b0 = __float2bfloat16(v0), b1 = __float2bfloat16(v1);
                bf16 b2 = __float2bfloat16(v2), b3 = __float2bfloat16(v3);
                __nv_bfloat162 pb0, pb1, ps0, ps1;
                pb0.x = b0; pb0.y = b1; pb1.x = b2; pb1.y = b3;
                ps0.x = __float2bfloat16(v0 - __bfloat162float(b0));
                ps0.y = __float2bfloat16(v1 - __bfloat162float(b1));
                ps1.x = __float2bfloat16(v2 - __bfloat162float(b2));
                ps1.y = __float2bfloat16(v3 - __bfloat162float(b3));
                *(__nv_bfloat162*)(Cb + (size_t)r0 * ldc + c0)       = pb0;
                *(__nv_bfloat162*)(Cb + (size_t)(r0 + 8) * ldc + c0) = pb1;
                *(__nv_bfloat162*)(Cs + (size_t)r0 * ldc + c0)       = ps0;
                *(__nv_bfloat162*)(Cs + (size_t)(r0 + 8) * ldc + c0) = ps1;
            } else {
                *(float2*)(Cf + (size_t)r0 * ldc + c0)       = make_float2(v0, v1);
                *(float2*)(Cf + (size_t)(r0 + 8) * ldc + c0) = make_float2(v2, v3);
            }
        }
    }
}

// ---------------- split fp32 -> bf16 big/small (8 floats/thread) -------------
__device__ __forceinline__ void split4(const float4 v, bf16* xb, bf16* xs, size_t i)
{
    bf16 b0 = __float2bfloat16(v.x), b1 = __float2bfloat16(v.y);
    bf16 b2 = __float2bfloat16(v.z), b3 = __float2bfloat16(v.w);
    __nv_bfloat162 pb0, pb1, ps0, ps1;
    pb0.x = b0; pb0.y = b1; pb1.x = b2; pb1.y = b3;
    ps0.x = __float2bfloat16(v.x - __bfloat162float(b0));
    ps0.y = __float2bfloat16(v.y - __bfloat162float(b1));
    ps1.x = __float2bfloat16(v.z - __bfloat162float(b2));
    ps1.y = __float2bfloat16(v.w - __bfloat162float(b3));
    *(__nv_bfloat162*)(xb + i)     = pb0;
    *(__nv_bfloat162*)(xb + i + 2) = pb1;
    *(__nv_bfloat162*)(xs + i)     = ps0;
    *(__nv_bfloat162*)(xs + i + 2) = ps1;
}

__global__ void split_kernel(const float* __restrict__ x,
                             bf16* __restrict__ xb, bf16* __restrict__ xs)
{
    size_t i = ((size_t)blockIdx.x * 256 + threadIdx.x) * 8;
    float4 v0 = *(const float4*)(x + i);
    float4 v1 = *(const float4*)(x + i + 4);
    split4(v0, xb, xs, i);
    split4(v1, xb, xs, i + 4);
}

__global__ void splitw_kernel(const float* __restrict__ W0, const float* __restrict__ W1,
                              const float* __restrict__ W2, const float* __restrict__ W3,
                              bf16* __restrict__ xb, bf16* __restrict__ xs)
{
    int w = blockIdx.y;
    const float* x = (w == 0) ? W0 : (w == 1) ? W1 : (w == 2) ? W2 : W3;
    size_t base = (size_t)w * HID * HID;
    size_t i = ((size_t)blockIdx.x * 256 + threadIdx.x) * 8;
    float4 v0 = *(const float4*)(x + i);
    float4 v1 = *(const float4*)(x + i + 4);
    split4(v0, xb + base, xs + base, i);
    split4(v1, xb + base, xs + base, i + 4);
}

// ---------------- MsPoE rotary -> split bf16 ---------------------------------
__global__ void rope_split_kernel(const float* __restrict__ q, const float* __restrict__ k,
                                  const int* __restrict__ pos_ids,
                                  bf16* __restrict__ qb, bf16* __restrict__ qs,
                                  bf16* __restrict__ kb, bf16* __restrict__ ks)
{
    int i = blockIdx.x * blockDim.x + threadIdx.x;
    int d = i & 63;
    int h = (i >> 6) & 31;
    int s = i >> 11;
    float ratio = 1.2f + (0.6f / 31.0f) * (float)h;
    float t = (float)pos_ids[s] / ratio;
    float inv_freq = exp2f(-(float)d * (13.287712379549449f / 64.0f));
    float f = t * inv_freq;
    float c, sn;
    sincosf(f, &sn, &c);
    size_t base = (size_t)s * HID + h * HD + d;

    float x1 = q[base], x2 = q[base + 64];
    float y0 = x1 * c - x2 * sn;
    float y1 = x2 * c + x1 * sn;
    bf16 t0 = __float2bfloat16(y0);
    bf16 t1 = __float2bfloat16(y1);
    qb[base] = t0;
    qs[base] = __float2bfloat16(y0 - __bfloat162float(t0));
    qb[base + 64] = t1;
    qs[base + 64] = __float2bfloat16(y1 - __bfloat162float(t1));

    x1 = k[base]; x2 = k[base + 64];
    y0 = x1 * c - x2 * sn;
    y1 = x2 * c + x1 * sn;
    t0 = __float2bfloat16(y0);
    t1 = __float2bfloat16(y1);
    kb[base] = t0;
    ks[base] = __float2bfloat16(y0 - __bfloat162float(t0));
    kb[base + 64] = t1;
    ks[base + 64] = __float2bfloat16(y1 - __bfloat162float(t1));
}

// ---------------- probs1: in-place softmax over k<=q --------------------------
__global__ void probs1_kernel(float* __restrict__ scores)
{
    int q = blockIdx.x, h = blockIdx.y;
    float* row = scores + ((size_t)h * S + q) * S;
    __shared__ float red[256];
    int tid = threadIdx.x;

    float v[8];
    float m = -INFINITY;
#pragma unroll
    for (int j = 0; j < 8; j++) {
        int k = tid + j * 256;
        v[j] = (k <= q) ? row[k] : -INFINITY;
        m = fmaxf(m, v[j]);
    }
    red[tid] = m;
    __syncthreads();
    for (int st = 128; st; st >>= 1) {
        if (tid < st) red[tid] = fmaxf(red[tid], red[tid + st]);
        __syncthreads();
    }
    m = red[0];
    __syncthreads();

    float sum = 0.f;
#pragma unroll
    for (int j = 0; j < 8; j++) {
        v[j] = expf(v[j] - m);
        sum += v[j];
    }
    red[tid] = sum;
    __syncthreads();
    for (int st = 128; st; st >>= 1) {
        if (tid < st) red[tid] += red[tid + st];
        __syncthreads();
    }
    float inv = 1.0f / red[0];
#pragma unroll
    for (int j = 0; j < 8; j++) {
        int k = tid + j * 256;
        if (k <= q) row[k] = v[j] * inv;
    }
}

// ---------------- hh partial sums over q-chunks (deterministic 2-pass) --------
__global__ void hh_part_kernel(const float* __restrict__ p1, float* __restrict__ part)
{
    int kb = blockIdx.x, qc = blockIdx.y, h = blockIdx.z;
    if (qc < kb) return;
    int k = kb * 256 + threadIdx.x;
    const float* base = p1 + (size_t)h * S * S;
    int q0 = qc * 256;
    float acc = 0.f;
    for (int q = q0; q < q0 + 256; q++) {
        if (q >= k) acc += base[(size_t)q * S + k];
    }
    part[((size_t)qc * NH + h) * S + k] = acc;
}

__global__ void hh_reduce_kernel(const float* __restrict__ part, float* __restrict__ hh)
{
    int h = blockIdx.y;
    int k = blockIdx.x * 256 + threadIdx.x;
    int kb = k >> 8;
    float acc = 0.f;
    for (int qc = kb; qc < 8; qc++)
        acc += part[((size_t)qc * NH + h) * S + k];
    hh[h * S + k] = acc;
}

// ---------------- per-head top-204 over hh[:SEL]; build key mask --------------
__global__ void topk_mask_kernel(const float* __restrict__ hh, float* __restrict__ mask)
{
    int h = blockIdx.x;
    int tid = threadIdx.x;
    __shared__ float vals[SEL];
    __shared__ float rmax[256];
    __shared__ int   ridx[256];

    for (int i = tid; i < SEL; i += 256) vals[i] = hh[h * S + i];
    for (int k = tid; k < S; k += 256)  mask[h * S + k] = (k >= SEL) ? 0.f : NEGV;
    __syncthreads();

    for (int it = 0; it < HHSZ; it++) {
        float bm = -INFINITY;
        int bi = SEL;
        for (int i = tid; i < SEL; i += 256) {
            float v = vals[i];
            if (v > bm) { bm = v; bi = i; }
        }
        rmax[tid] = bm;
        ridx[tid] = bi;
        __syncthreads();
        for (int st = 128; st; st >>= 1) {
            if (tid < st) {
                if (rmax[tid + st] > rmax[tid] ||
                    (rmax[tid + st] == rmax[tid] && ridx[tid + st] < ridx[tid])) {
                    rmax[tid] = rmax[tid + st];
                    ridx[tid] = ridx[tid + st];
                }
            }
            __syncthreads();
        }
        if (tid == 0) {
            int kk = ridx[0];
            mask[h * S + kk] = 0.f;
            vals[kk] = -INFINITY;
        }
        __syncthreads();
    }
}

// ---------------- softmax2 = renormalize kept probs1; split bf16 out ----------
__global__ void softmax2_renorm_kernel(const float* __restrict__ p1,
                                       const float* __restrict__ mask,
                                       bf16* __restrict__ pb, bf16* __restrict__ ps)
{
    int q = blockIdx.x, h = blockIdx.y;
    size_t off = ((size_t)h * S + q) * S;
    const float* row = p1 + off;
    const float* mk = mask + h * S;
    __shared__ float red[256];
    int tid = threadIdx.x;
    int tend = ((q >> 7) + 1) << 7;

    float v[8];
    float sum = 0.f;
#pragma unroll
    for (int j = 0; j < 8; j++) {
        int k = tid + j * 256;
        bool kept = (k <= q) && ((mk[k] == 0.f) || (k == q));
        v[j] = kept ? row[k] : 0.f;
        sum += v[j];
    }
    red[tid] = sum;
    __syncthreads();
    for (int st = 128; st; st >>= 1) {
        if (tid < st) red[tid] += red[tid + st];
        __syncthreads();
    }
    float inv = 1.0f / red[0];
#pragma unroll
    for (int j = 0; j < 8; j++) {
        int k = tid + j * 256;
        if (k < tend) {
            float val = v[j] * inv;
            bf16 b = __float2bfloat16(val);
            pb[off + k] = b;
            ps[off + k] = __float2bfloat16(val - __bfloat162float(b));
        }
    }
}

// ---------------- launch -------------------------------------------------------
extern "C" void kernel_launch(void* const* d_in, const int* in_sizes, int n_in,
                              void* d_out, int out_size)
{
    const float* hs = (const float*)d_in[0];
    const float* W0 = (const float*)d_in[1];
    const float* W1 = (const float*)d_in[2];
    const float* W2 = (const float*)d_in[3];
    const float* W3 = (const float*)d_in[4];
    const int* pos = (const int*)d_in[5];
    float* out = (float*)d_out;

    float *q, *k, *scores, *hh, *hhp, *mask;
    bf16 *hsb, *hss, *wb, *ws, *qb, *qs, *kb, *ks, *vb, *vs, *pb, *ps, *ab, *as;
    cudaGetSymbolAddress((void**)&q, g_q);
    cudaGetSymbolAddress((void**)&k, g_k);
    cudaGetSymbolAddress((void**)&scores, g_scores);
    cudaGetSymbolAddress((void**)&hh, g_hh);
    cudaGetSymbolAddress((void**)&hhp, g_hhpart);
    cudaGetSymbolAddress((void**)&mask, g_mask);
    cudaGetSymbolAddress((void**)&hsb, g_hs_b);
    cudaGetSymbolAddress((void**)&hss, g_hs_s);
    cudaGetSymbolAddress((void**)&wb, g_w_b);
    cudaGetSymbolAddress((void**)&ws, g_w_s);
    cudaGetSymbolAddress((void**)&qb, g_qb);
    cudaGetSymbolAddress((void**)&qs, g_qs);
    cudaGetSymbolAddress((void**)&kb, g_kb);
    cudaGetSymbolAddress((void**)&ks, g_ks);
    cudaGetSymbolAddress((void**)&vb, g_vb);
    cudaGetSymbolAddress((void**)&vs, g_vs);
    cudaGetSymbolAddress((void**)&pb, g_pb);
    cudaGetSymbolAddress((void**)&ps, g_ps);
    cudaGetSymbolAddress((void**)&ab, g_ab);
    cudaGetSymbolAddress((void**)&as, g_as);

    const int SM_NT = (2 * (2 * ASZ + 2 * 128 * BNT_ST)) * 4;
    const int SM_NN = (2 * (2 * ASZ + 2 * 32 * BNN_ST)) * 4;
    cudaFuncSetAttribute(gemm_bf3<true, 0, false, true>,  cudaFuncAttributeMaxDynamicSharedMemorySize, SM_NT);
    cudaFuncSetAttribute(gemm_bf3<false, 2, true, false>, cudaFuncAttributeMaxDynamicSharedMemorySize, SM_NN);
    cudaFuncSetAttribute(gemm_big<0>, cudaFuncAttributeMaxDynamicSharedMemorySize, GB_SMEM);
    cudaFuncSetAttribute(gemm_big<2>, cudaFuncAttributeMaxDynamicSharedMemorySize, GB_SMEM);

    // splits (8 floats/thread)
    split_kernel<<<(S * HID) / 2048, 256>>>(hs, hsb, hss);
    splitw_kernel<<<dim3((HID * HID) / 2048, 4), 256>>>(W0, W1, W2, W3, wb, ws);

    // projections: 256x128 tile, 512 threads
    dim3 gbig(HID / 128, S / 256);
    gemm_big<0><<<gbig, 512, GB_SMEM>>>(hsb, hss, HID,
        wb + 0 * (size_t)HID * HID, ws + 0 * (size_t)HID * HID, HID,
        q, (bf16*)0, (bf16*)0, HID, HID);
    gemm_big<0><<<gbig, 512, GB_SMEM>>>(hsb, hss, HID,
        wb + 1 * (size_t)HID * HID, ws + 1 * (size_t)HID * HID, HID,
        k, (bf16*)0, (bf16*)0, HID, HID);
    gemm_big<2><<<gbig, 512, GB_SMEM>>>(hsb, hss, HID,
        wb + 2 * (size_t)HID * HID, ws + 2 * (size_t)HID * HID, HID,
        (float*)0, vb, vs, HID, HID);

    rope_split_kernel<<<(S * NH * 64) / 256, 256>>>(q, k, pos, qb, qs, kb, ks);

    // QK^T lower-triangle tiles only
    dim3 gs(136, 1, NH);
    gemm_bf3<true, 0, false, true><<<gs, 256, SM_NT>>>(
        qb, qs, HID, (size_t)HD, kb, ks, HID, (size_t)HD,
        scores, (bf16*)0, (bf16*)0, S, (size_t)S * S, HD, 0.08838834764831845f);

    probs1_kernel<<<dim3(S, NH), 256>>>(scores);
    hh_part_kernel<<<dim3(8, 8, NH), 256>>>(scores, hhp);
    hh_reduce_kernel<<<dim3(8, NH), 256>>>(hhp, hh);
    topk_mask_kernel<<<NH, 256>>>(hh, mask);
    softmax2_renorm_kernel<<<dim3(S, NH), 256>>>(scores, mask, pb, ps);

    // PV (K truncated at diagonal, heavy tiles first)
    dim3 gpv(HD / BN, 16, NH);
    gemm_bf3<false, 2, true, false><<<gpv, 256, SM_NN>>>(
        pb, ps, S, (size_t)S * S, vb, vs, HID, (size_t)HD,
        (float*)0, ab, as, HID, (size_t)HD, S, 1.f);

    // O projection
    gemm_big<0><<<gbig, 512, GB_SMEM>>>(ab, as, HID,
        wb + 3 * (size_t)HID * HID, ws + 3 * (size_t)HID * HID, HID,
        out, (bf16*)0, (bf16*)0, HID, HID);
}